// round 15
// baseline (speedup 1.0000x reference)
#include <cuda_runtime.h>
#include <cuda_bf16.h>
#include <math.h>
#include <stdint.h>

#define N_NODES 114688
#define N_EDGES 917504
#define MAXC    256
#define BN_EPS  1e-5f
#define ONE_STEP 14
#define NGRAPH  (N_NODES / ONE_STEP)
#define NBLK    448              // N_NODES / 256

// ---------------- scratch (static device globals; no allocation) ----------------
__device__ __align__(16) float  g_buf0[(size_t)N_NODES * MAXC];
__device__ __align__(16) float  g_buf1[(size_t)N_NODES * MAXC];
__device__ __align__(16) float  g_buf2[(size_t)N_NODES * MAXC];
__device__ float  g_dis[N_NODES];
__device__ double g_sum[6 * MAXC], g_sumsq[6 * MAXC];   // 6 zones: L1,L2,L3,L4,G1,G2
__device__ __align__(16) float g_scaleA[MAXC], g_shiftA[MAXC];
__device__ __align__(16) float g_scale4[32],  g_shift4[32];
__device__ __align__(16) float g_scaleG1[16], g_shiftG1[16];
__device__ __align__(16) float g_scaleG2[4],  g_shiftG2[4];
// CSR scratch
__device__ int g_cnt[N_NODES];
__device__ int g_rowptr[N_NODES + 1];
__device__ int g_cursor[N_NODES];
__device__ int g_ssrc[N_EDGES];
__device__ int g_bsum[NBLK];

__device__ __forceinline__ uint32_t pack_bf16x2(float a, float b) {
    uint32_t r;
    asm("cvt.rn.bf16x2.f32 %0, %1, %2;" : "=r"(r) : "f"(b), "f"(a));
    return r;
}
__device__ __forceinline__ void split2_bf16(float v0, float v1, uint32_t& h, uint32_t& l) {
    float h0 = __bfloat162float(__float2bfloat16(v0));
    float h1 = __bfloat162float(__float2bfloat16(v1));
    h = pack_bf16x2(h0, h1);
    l = pack_bf16x2(v0 - h0, v1 - h1);
}
__device__ __forceinline__ void mma_bf16(float* c, const uint32_t* a, uint32_t b0, uint32_t b1) {
    asm volatile(
        "mma.sync.aligned.m16n8k16.row.col.f32.bf16.bf16.f32 "
        "{%0,%1,%2,%3}, {%4,%5,%6,%7}, {%8,%9}, {%0,%1,%2,%3};"
        : "+f"(c[0]), "+f"(c[1]), "+f"(c[2]), "+f"(c[3])
        : "r"(a[0]), "r"(a[1]), "r"(a[2]), "r"(a[3]), "r"(b0), "r"(b1));
}

// ---------------- CSR build (+ stats-zone zeroing) ----------------
__global__ void cnt_zero_kernel() {
    int i = blockIdx.x * 256 + threadIdx.x;
    if (i < N_NODES) g_cnt[i] = 0;
    if (blockIdx.x < 6) {
        int z = blockIdx.x * 256 + threadIdx.x;
        g_sum[z] = 0.0;
        g_sumsq[z] = 0.0;
    }
}
__global__ void cnt_count_kernel(const int* __restrict__ ei) {
    int e = blockIdx.x * 256 + threadIdx.x;
    if (e < N_EDGES) atomicAdd(&g_cnt[ei[N_EDGES + e]], 1);
}
__global__ void dis_kernel() {
    int i = blockIdx.x * 256 + threadIdx.x;
    if (i < N_NODES) g_dis[i] = rsqrtf((float)g_cnt[i] + 1.0f);
}
__global__ void scan1_kernel() {
    __shared__ int sh[256];
    int tid = threadIdx.x;
    int i = blockIdx.x * 256 + tid;
    int v = g_cnt[i];
    sh[tid] = v;
    __syncthreads();
#pragma unroll
    for (int off = 1; off < 256; off <<= 1) {
        int t = (tid >= off) ? sh[tid - off] : 0;
        __syncthreads();
        sh[tid] += t;
        __syncthreads();
    }
    g_rowptr[i] = sh[tid] - v;
    if (tid == 255) g_bsum[blockIdx.x] = sh[255];
}
__global__ void scan2_kernel() {
    __shared__ int sh[512];
    int tid = threadIdx.x;
    int v = (tid < NBLK) ? g_bsum[tid] : 0;
    sh[tid] = v;
    __syncthreads();
#pragma unroll
    for (int off = 1; off < 512; off <<= 1) {
        int t = (tid >= off) ? sh[tid - off] : 0;
        __syncthreads();
        sh[tid] += t;
        __syncthreads();
    }
    if (tid < NBLK) g_bsum[tid] = sh[tid] - v;
}
__global__ void scan3_kernel() {
    int i = blockIdx.x * 256 + threadIdx.x;
    int r = g_rowptr[i] + g_bsum[blockIdx.x];
    g_rowptr[i] = r;
    g_cursor[i] = r;
    if (i == 0) g_rowptr[N_NODES] = N_EDGES;
}
__global__ void scatter_kernel(const int* __restrict__ ei) {
    int e = blockIdx.x * 256 + threadIdx.x;
    if (e < N_EDGES) {
        int dst = ei[N_EDGES + e];
        int pos = atomicAdd(&g_cursor[dst], 1);
        g_ssrc[pos] = ei[e];
    }
}

// ---------------- CSR aggregation ----------------
template<int C, bool AFFINE, bool COMBINE>
__global__ __launch_bounds__(256)
void csr_agg_kernel(const float* __restrict__ z, const float* __restrict__ b,
                    float* __restrict__ out, int zone) {
    const int c4n = C / 4;
    const int DPW = 32 / c4n;
    const int DPB = DPW * 8;
    int lane = threadIdx.x & 31, wid = threadIdx.x >> 5;
    int sub = lane / c4n, cc = lane % c4n;
    float4 bb = make_float4(0.f, 0.f, 0.f, 0.f), sc, sf;
    if (COMBINE) bb = ((const float4*)b)[cc];
    if (AFFINE) { sc = ((const float4*)g_scaleA)[cc]; sf = ((const float4*)g_shiftA)[cc]; }
    float s[4] = {0, 0, 0, 0}, q[4] = {0, 0, 0, 0};

    for (int d0 = blockIdx.x * DPB; d0 < N_NODES; d0 += gridDim.x * DPB) {
        int dst = d0 + wid * DPW + sub;
        float dd = g_dis[dst];
        int beg = g_rowptr[dst], end = g_rowptr[dst + 1];
        float4 vz = *((const float4*)(z + (size_t)dst * C) + cc);
        if (AFFINE) {
            vz.x = fmaf(vz.x, sc.x, sf.x);
            vz.y = fmaf(vz.y, sc.y, sf.y);
            vz.z = fmaf(vz.z, sc.z, sf.z);
            vz.w = fmaf(vz.w, sc.w, sf.w);
        }
        float ss = dd * dd;
        float4 acc = make_float4(vz.x * ss, vz.y * ss, vz.z * ss, vz.w * ss);
        int i = beg;
        for (; i + 3 < end; i += 4) {
            int s0 = g_ssrc[i], s1 = g_ssrc[i + 1], s2 = g_ssrc[i + 2], s3 = g_ssrc[i + 3];
            float n0 = g_dis[s0] * dd, n1 = g_dis[s1] * dd;
            float n2 = g_dis[s2] * dd, n3 = g_dis[s3] * dd;
            float4 v0 = *((const float4*)(z + (size_t)s0 * C) + cc);
            float4 v1 = *((const float4*)(z + (size_t)s1 * C) + cc);
            float4 v2 = *((const float4*)(z + (size_t)s2 * C) + cc);
            float4 v3 = *((const float4*)(z + (size_t)s3 * C) + cc);
            if (AFFINE) {
                v0.x = fmaf(v0.x, sc.x, sf.x); v0.y = fmaf(v0.y, sc.y, sf.y);
                v0.z = fmaf(v0.z, sc.z, sf.z); v0.w = fmaf(v0.w, sc.w, sf.w);
                v1.x = fmaf(v1.x, sc.x, sf.x); v1.y = fmaf(v1.y, sc.y, sf.y);
                v1.z = fmaf(v1.z, sc.z, sf.z); v1.w = fmaf(v1.w, sc.w, sf.w);
                v2.x = fmaf(v2.x, sc.x, sf.x); v2.y = fmaf(v2.y, sc.y, sf.y);
                v2.z = fmaf(v2.z, sc.z, sf.z); v2.w = fmaf(v2.w, sc.w, sf.w);
                v3.x = fmaf(v3.x, sc.x, sf.x); v3.y = fmaf(v3.y, sc.y, sf.y);
                v3.z = fmaf(v3.z, sc.z, sf.z); v3.w = fmaf(v3.w, sc.w, sf.w);
            }
            acc.x = fmaf(v0.x, n0, fmaf(v1.x, n1, fmaf(v2.x, n2, fmaf(v3.x, n3, acc.x))));
            acc.y = fmaf(v0.y, n0, fmaf(v1.y, n1, fmaf(v2.y, n2, fmaf(v3.y, n3, acc.y))));
            acc.z = fmaf(v0.z, n0, fmaf(v1.z, n1, fmaf(v2.z, n2, fmaf(v3.z, n3, acc.z))));
            acc.w = fmaf(v0.w, n0, fmaf(v1.w, n1, fmaf(v2.w, n2, fmaf(v3.w, n3, acc.w))));
        }
        for (; i < end; i++) {
            int s0 = g_ssrc[i];
            float n0 = g_dis[s0] * dd;
            float4 v0 = *((const float4*)(z + (size_t)s0 * C) + cc);
            if (AFFINE) {
                v0.x = fmaf(v0.x, sc.x, sf.x); v0.y = fmaf(v0.y, sc.y, sf.y);
                v0.z = fmaf(v0.z, sc.z, sf.z); v0.w = fmaf(v0.w, sc.w, sf.w);
            }
            acc.x = fmaf(v0.x, n0, acc.x);
            acc.y = fmaf(v0.y, n0, acc.y);
            acc.z = fmaf(v0.z, n0, acc.z);
            acc.w = fmaf(v0.w, n0, acc.w);
        }
        if (COMBINE) {
            acc.x = fmaxf(acc.x + bb.x, 0.f);
            acc.y = fmaxf(acc.y + bb.y, 0.f);
            acc.z = fmaxf(acc.z + bb.z, 0.f);
            acc.w = fmaxf(acc.w + bb.w, 0.f);
            s[0] += acc.x; q[0] += acc.x * acc.x;
            s[1] += acc.y; q[1] += acc.y * acc.y;
            s[2] += acc.z; q[2] += acc.z * acc.z;
            s[3] += acc.w; q[3] += acc.w * acc.w;
        }
        *((float4*)(out + (size_t)dst * C) + cc) = acc;
    }
    if (COMBINE) {
        __shared__ float csum[C], csq[C];
        for (int i = threadIdx.x; i < C; i += 256) { csum[i] = 0.f; csq[i] = 0.f; }
        __syncthreads();
#pragma unroll
        for (int j = 0; j < 4; j++) {
            atomicAdd(&csum[cc * 4 + j], s[j]);
            atomicAdd(&csq[cc * 4 + j],  q[j]);
        }
        __syncthreads();
        for (int i = threadIdx.x; i < C; i += 256) {
            atomicAdd(&g_sum[zone * MAXC + i],   (double)csum[i]);
            atomicAdd(&g_sumsq[zone * MAXC + i], (double)csq[i]);
        }
    }
}

// ---------------- 3xBF16 mma.sync GEMM (m16n8k16, split-at-store) ----------------
// EPI 0: out = z.  EPI 1: out = relu(z + bias), BN stats accumulated to zone.
template<int CO, int BN, int K, bool AFFINE, int EPI>
__global__ __launch_bounds__(256, 2)
void mma_gemm_kernel(const float* __restrict__ A, const float* __restrict__ W,
                     const float* __restrict__ bias, float* __restrict__ out, int zone) {
    const int ASTR = 20;
    const int BSTR = 20;
    const int AW = 128 * ASTR;
    const int BW = BN * BSTR;
    extern __shared__ uint32_t sm[];
    uint32_t* const Ah = sm;
    uint32_t* const Al = sm + AW;
    uint32_t* const Bh = sm + 2 * AW;
    uint32_t* const Bl = sm + 2 * AW + BW;
    float* const scs = (float*)(sm + 2 * AW + 2 * BW);
    float* const sfs = scs + (AFFINE ? K : 0);
    float* const ssum = (float*)(sm + 2 * AW + 2 * BW + (AFFINE ? 2 * K : 0));
    float* const ssq  = ssum + BN;

    const int tid = threadIdx.x;
    const int lane = tid & 31, wid = tid >> 5;
    const int warpM = wid & 3, warpN = wid >> 2;
    const int WN = BN / 2;
    const int NT = WN / 8;
    const int g = lane >> 2, kk = lane & 3;
    const int row0 = blockIdx.y * 128;
    const int col0 = blockIdx.x * BN;

    if (AFFINE) {
        for (int i = tid; i < K; i += 256) { scs[i] = g_scaleA[i]; sfs[i] = g_shiftA[i]; }
    }
    if (EPI == 1) {
        for (int i = tid; i < BN; i += 256) { ssum[i] = 0.f; ssq[i] = 0.f; }
    }
    if (AFFINE || EPI == 1) __syncthreads();

    float acc[2][NT][4];
#pragma unroll
    for (int t = 0; t < 2; t++)
#pragma unroll
        for (int j = 0; j < NT; j++)
#pragma unroll
            for (int q = 0; q < 4; q++) acc[t][j][q] = 0.f;

    const int NCH = K / 32;
    for (int ch = 0; ch < NCH; ch++) {
        const int k0 = ch * 32;
        if (ch) __syncthreads();
        // A tile: 128 rows x 32 k -> bf16 hi/lo pairs
#pragma unroll
        for (int i = 0; i < 4; i++) {
            int f = tid + i * 256;
            int r = f >> 3;
            int kq = (f & 7) * 4;
            float4 v = *(const float4*)(A + (size_t)(row0 + r) * K + k0 + kq);
            if (AFFINE) {
                v.x = fmaf(v.x, scs[k0 + kq + 0], sfs[k0 + kq + 0]);
                v.y = fmaf(v.y, scs[k0 + kq + 1], sfs[k0 + kq + 1]);
                v.z = fmaf(v.z, scs[k0 + kq + 2], sfs[k0 + kq + 2]);
                v.w = fmaf(v.w, scs[k0 + kq + 3], sfs[k0 + kq + 3]);
            }
            uint32_t h0, l0, h1, l1;
            split2_bf16(v.x, v.y, h0, l0);
            split2_bf16(v.z, v.w, h1, l1);
            int p = kq >> 1;
            Ah[r * ASTR + p] = h0; Ah[r * ASTR + p + 1] = h1;
            Al[r * ASTR + p] = l0; Al[r * ASTR + p + 1] = l1;
        }
        // B tile: 32 k x BN cols -> [n][kpair] bf16 hi/lo
        const int NBT = BN / 64;
#pragma unroll
        for (int i = 0; i < NBT; i++) {
            int f = tid + i * 256;
            int pr = f & 15;
            int c = (f >> 4) * 4;
            const float* Wp = W + (size_t)(k0 + 2 * pr) * CO + col0 + c;
            float4 w0 = *(const float4*)Wp;
            float4 w1 = *(const float4*)(Wp + CO);
            uint32_t h, l;
            split2_bf16(w0.x, w1.x, h, l);
            Bh[(c + 0) * BSTR + pr] = h; Bl[(c + 0) * BSTR + pr] = l;
            split2_bf16(w0.y, w1.y, h, l);
            Bh[(c + 1) * BSTR + pr] = h; Bl[(c + 1) * BSTR + pr] = l;
            split2_bf16(w0.z, w1.z, h, l);
            Bh[(c + 2) * BSTR + pr] = h; Bl[(c + 2) * BSTR + pr] = l;
            split2_bf16(w0.w, w1.w, h, l);
            Bh[(c + 3) * BSTR + pr] = h; Bl[(c + 3) * BSTR + pr] = l;
        }
        __syncthreads();
#pragma unroll
        for (int ks = 0; ks < 2; ks++) {
            const int kp = ks * 8;
#pragma unroll
            for (int t = 0; t < 2; t++) {
                const int r = warpM * 32 + t * 16 + g;
                uint32_t ah[4], al[4];
                ah[0] = Ah[r * ASTR + kp + kk];
                ah[1] = Ah[(r + 8) * ASTR + kp + kk];
                ah[2] = Ah[r * ASTR + kp + kk + 4];
                ah[3] = Ah[(r + 8) * ASTR + kp + kk + 4];
                al[0] = Al[r * ASTR + kp + kk];
                al[1] = Al[(r + 8) * ASTR + kp + kk];
                al[2] = Al[r * ASTR + kp + kk + 4];
                al[3] = Al[(r + 8) * ASTR + kp + kk + 4];
#pragma unroll
                for (int j = 0; j < NT; j++) {
                    int n = warpN * WN + j * 8 + g;
                    uint32_t b0h = Bh[n * BSTR + kp + kk];
                    uint32_t b1h = Bh[n * BSTR + kp + kk + 4];
                    uint32_t b0l = Bl[n * BSTR + kp + kk];
                    uint32_t b1l = Bl[n * BSTR + kp + kk + 4];
                    mma_bf16(acc[t][j], ah, b0h, b1h);
                    mma_bf16(acc[t][j], al, b0h, b1h);
                    mma_bf16(acc[t][j], ah, b0l, b1l);
                }
            }
        }
    }

    // epilogue
#pragma unroll
    for (int j = 0; j < NT; j++) {
        const int cl = warpN * WN + j * 8 + 2 * kk;
        const int c = col0 + cl;
        float s0 = 0.f, q0 = 0.f, s1 = 0.f, q1 = 0.f;
#pragma unroll
        for (int t = 0; t < 2; t++) {
            const int r = row0 + warpM * 32 + t * 16 + g;
            float2 v1 = make_float2(acc[t][j][0], acc[t][j][1]);
            float2 v2 = make_float2(acc[t][j][2], acc[t][j][3]);
            if (EPI == 1) {
                float2 bb = *(const float2*)(bias + c);
                v1.x = fmaxf(v1.x + bb.x, 0.f);
                v1.y = fmaxf(v1.y + bb.y, 0.f);
                v2.x = fmaxf(v2.x + bb.x, 0.f);
                v2.y = fmaxf(v2.y + bb.y, 0.f);
                s0 += v1.x + v2.x; q0 += v1.x * v1.x + v2.x * v2.x;
                s1 += v1.y + v2.y; q1 += v1.y * v1.y + v2.y * v2.y;
            }
            *(float2*)(out + (size_t)r * CO + c) = v1;
            *(float2*)(out + (size_t)(r + 8) * CO + c) = v2;
        }
        if (EPI == 1) {
            atomicAdd(&ssum[cl],     s0); atomicAdd(&ssq[cl],     q0);
            atomicAdd(&ssum[cl + 1], s1); atomicAdd(&ssq[cl + 1], q1);
        }
    }
    if (EPI == 1) {
        __syncthreads();
        for (int i = tid; i < BN; i += 256) {
            atomicAdd(&g_sum[zone * MAXC + col0 + i],   (double)ssum[i]);
            atomicAdd(&g_sumsq[zone * MAXC + col0 + i], (double)ssq[i]);
        }
    }
}

// ---------------- fp32 GEMM (layer 4: 64 -> 32), writes z only ----------------
template<int BN_T, int TN_T, bool AFFINE>
__global__ __launch_bounds__(256, 2)
void gemm_kernel(const float* __restrict__ A, const float* __restrict__ W,
                 float* __restrict__ out, int K, int Co) {
    __shared__ float As[16][128];
    __shared__ float Ws[16][BN_T];
    __shared__ float sc_sh[256], sf_sh[256];
    int tid = threadIdx.x;
    int tx = tid & 15, ty = tid >> 4;
    int row0 = blockIdx.y * 128;
    int col0 = blockIdx.x * BN_T;
    if (AFFINE) {
        for (int i = tid; i < K; i += 256) { sc_sh[i] = g_scaleA[i]; sf_sh[i] = g_shiftA[i]; }
    }
    float acc[8][TN_T];
#pragma unroll
    for (int i = 0; i < 8; i++)
#pragma unroll
        for (int j = 0; j < TN_T; j++) acc[i][j] = 0.f;
    if (AFFINE) __syncthreads();
    for (int k0 = 0; k0 < K; k0 += 16) {
#pragma unroll
        for (int i = 0; i < 2; i++) {
            int f = tid * 2 + i;
            int r = f >> 2;
            int kq = (f & 3) * 4;
            float4 v = *(const float4*)(A + (size_t)(row0 + r) * K + k0 + kq);
            if (AFFINE) {
                v.x = fmaf(v.x, sc_sh[k0 + kq + 0], sf_sh[k0 + kq + 0]);
                v.y = fmaf(v.y, sc_sh[k0 + kq + 1], sf_sh[k0 + kq + 1]);
                v.z = fmaf(v.z, sc_sh[k0 + kq + 2], sf_sh[k0 + kq + 2]);
                v.w = fmaf(v.w, sc_sh[k0 + kq + 3], sf_sh[k0 + kq + 3]);
            }
            As[kq + 0][r] = v.x; As[kq + 1][r] = v.y;
            As[kq + 2][r] = v.z; As[kq + 3][r] = v.w;
        }
        {
            const int NF4 = 16 * BN_T / 4;
#pragma unroll
            for (int i = 0; i < (NF4 + 255) / 256; i++) {
                int f = tid + i * 256;
                if ((NF4 % 256 == 0) || f < NF4) {
                    int k = f / (BN_T / 4);
                    int c = (f % (BN_T / 4)) * 4;
                    float4 v = *(const float4*)(W + (size_t)(k0 + k) * Co + col0 + c);
                    Ws[k][c + 0] = v.x; Ws[k][c + 1] = v.y;
                    Ws[k][c + 2] = v.z; Ws[k][c + 3] = v.w;
                }
            }
        }
        __syncthreads();
#pragma unroll
        for (int kk = 0; kk < 16; kk++) {
            float a[8], w[TN_T];
            float4 a0 = *(const float4*)&As[kk][ty * 4];
            float4 a1 = *(const float4*)&As[kk][64 + ty * 4];
            a[0] = a0.x; a[1] = a0.y; a[2] = a0.z; a[3] = a0.w;
            a[4] = a1.x; a[5] = a1.y; a[6] = a1.z; a[7] = a1.w;
            if (TN_T == 4) {
                float4 w0 = *(const float4*)&Ws[kk][tx * 4];
                w[0] = w0.x; w[1] = w0.y; w[2] = w0.z; w[3] = w0.w;
            } else {
                float2 w0 = *(const float2*)&Ws[kk][tx * 2];
                w[0] = w0.x; w[1] = w0.y;
            }
#pragma unroll
            for (int i = 0; i < 8; i++)
#pragma unroll
                for (int j = 0; j < TN_T; j++) acc[i][j] = fmaf(a[i], w[j], acc[i][j]);
        }
        __syncthreads();
    }
#pragma unroll
    for (int i = 0; i < 8; i++) {
        int r = row0 + ((i < 4) ? (ty * 4 + i) : (64 + ty * 4 + i - 4));
        if (TN_T >= 4) {
            int c = col0 + tx * 4;
            *(float4*)(out + (size_t)r * Co + c) =
                make_float4(acc[i][0], acc[i][1], acc[i][2], acc[i][3]);
        } else {
            int c = col0 + tx * 2;
            *(float2*)(out + (size_t)r * Co + c) = make_float2(acc[i][0], acc[i][1]);
        }
    }
}

// ---------------- BN finalize ----------------
__global__ void bn_finalize_kernel(const float* __restrict__ gam, const float* __restrict__ bet,
                                   int C, float* __restrict__ oS, float* __restrict__ oH,
                                   int zone) {
    int c = threadIdx.x;
    if (c >= C) return;
    double mean = g_sum[zone * MAXC + c] / (double)N_NODES;
    double var = g_sumsq[zone * MAXC + c] / (double)N_NODES - mean * mean;
    double sc = (double)gam[c] / sqrt(var + (double)BN_EPS);
    oS[c] = (float)sc;
    oH[c] = bet[c] - (float)(mean * sc);
}

// ---------------- gate network (stats fused) ----------------
__global__ void gate1_kernel(const float* __restrict__ y4, const float* __restrict__ gW1,
                             const float* __restrict__ gb1, float* __restrict__ outz) {
    __shared__ float w[32 * 16];
    __shared__ float bb[16], sc[32], sf[32];
    __shared__ float csum[16], csq[16];
    int tid = threadIdx.x;
    int lane = tid & 31;
    for (int i = tid; i < 512; i += 256) w[i] = gW1[i];
    if (tid < 16) { bb[tid] = gb1[tid]; csum[tid] = 0.f; csq[tid] = 0.f; }
    if (tid < 32) { sc[tid] = g_scale4[tid]; sf[tid] = g_shift4[tid]; }
    __syncthreads();
    int row = blockIdx.x * 256 + tid;
    float h[32];
#pragma unroll
    for (int k4 = 0; k4 < 8; k4++) {
        float4 v = *((const float4*)(y4 + (size_t)row * 32) + k4);
        h[k4 * 4 + 0] = fmaf(v.x, sc[k4 * 4 + 0], sf[k4 * 4 + 0]);
        h[k4 * 4 + 1] = fmaf(v.y, sc[k4 * 4 + 1], sf[k4 * 4 + 1]);
        h[k4 * 4 + 2] = fmaf(v.z, sc[k4 * 4 + 2], sf[k4 * 4 + 2]);
        h[k4 * 4 + 3] = fmaf(v.w, sc[k4 * 4 + 3], sf[k4 * 4 + 3]);
    }
    float acc[16];
#pragma unroll
    for (int j = 0; j < 16; j++) acc[j] = bb[j];
#pragma unroll
    for (int k = 0; k < 32; k++)
#pragma unroll
        for (int j = 0; j < 16; j++) acc[j] = fmaf(h[k], w[k * 16 + j], acc[j]);
#pragma unroll
    for (int j4 = 0; j4 < 4; j4++)
        *((float4*)(outz + (size_t)row * 16) + j4) =
            make_float4(acc[j4 * 4], acc[j4 * 4 + 1], acc[j4 * 4 + 2], acc[j4 * 4 + 3]);
    // fused stats: warp-shfl reduce per channel, then smem, then global
#pragma unroll
    for (int j = 0; j < 16; j++) {
        float sv = acc[j], qv = acc[j] * acc[j];
#pragma unroll
        for (int o = 16; o; o >>= 1) {
            sv += __shfl_xor_sync(0xffffffffu, sv, o);
            qv += __shfl_xor_sync(0xffffffffu, qv, o);
        }
        if (lane == 0) { atomicAdd(&csum[j], sv); atomicAdd(&csq[j], qv); }
    }
    __syncthreads();
    if (tid < 16) {
        atomicAdd(&g_sum[4 * MAXC + tid],   (double)csum[tid]);
        atomicAdd(&g_sumsq[4 * MAXC + tid], (double)csq[tid]);
    }
}

__global__ void gate2_kernel(const float* __restrict__ z, const float* __restrict__ gW2,
                             const float* __restrict__ gb2, float* __restrict__ out) {
    __shared__ float w[16], sc[16], sf[16], b0;
    __shared__ float ws[8], wq[8];
    int tid = threadIdx.x;
    int lane = tid & 31, wid = tid >> 5;
    if (tid < 16) { w[tid] = gW2[tid]; sc[tid] = g_scaleG1[tid]; sf[tid] = g_shiftG1[tid]; }
    if (tid == 0) b0 = gb2[0];
    __syncthreads();
    int row = blockIdx.x * 256 + tid;
    float acc = b0;
#pragma unroll
    for (int k4 = 0; k4 < 4; k4++) {
        float4 v = *((const float4*)(z + (size_t)row * 16) + k4);
        acc = fmaf(fmaxf(fmaf(v.x, sc[k4 * 4 + 0], sf[k4 * 4 + 0]), 0.f), w[k4 * 4 + 0], acc);
        acc = fmaf(fmaxf(fmaf(v.y, sc[k4 * 4 + 1], sf[k4 * 4 + 1]), 0.f), w[k4 * 4 + 1], acc);
        acc = fmaf(fmaxf(fmaf(v.z, sc[k4 * 4 + 2], sf[k4 * 4 + 2]), 0.f), w[k4 * 4 + 2], acc);
        acc = fmaf(fmaxf(fmaf(v.w, sc[k4 * 4 + 3], sf[k4 * 4 + 3]), 0.f), w[k4 * 4 + 3], acc);
    }
    out[row] = acc;
    // fused stats (scalar channel)
    float sv = acc, qv = acc * acc;
#pragma unroll
    for (int o = 16; o; o >>= 1) {
        sv += __shfl_xor_sync(0xffffffffu, sv, o);
        qv += __shfl_xor_sync(0xffffffffu, qv, o);
    }
    if (lane == 0) { ws[wid] = sv; wq[wid] = qv; }
    __syncthreads();
    if (tid == 0) {
        float ts = 0.f, tq = 0.f;
#pragma unroll
        for (int i = 0; i < 8; i++) { ts += ws[i]; tq += wq[i]; }
        atomicAdd(&g_sum[5 * MAXC],   (double)ts);
        atomicAdd(&g_sumsq[5 * MAXC], (double)tq);
    }
}

// ---------------- pooling + FC + softmax ----------------
__global__ void pool_fc_kernel(const float* __restrict__ y4, const float* __restrict__ g2,
                               const float* __restrict__ fcW, const float* __restrict__ fcb,
                               float* __restrict__ out) {
    int warp = (blockIdx.x * blockDim.x + threadIdx.x) >> 5;
    int lane = threadIdx.x & 31;
    if (warp >= NGRAPH) return;
    int n0 = warp * ONE_STEP;
    const unsigned FULL = 0xffffffffu;
    float scG = g_scaleG2[0], sfG = g_shiftG2[0];
    float gv = (lane < ONE_STEP) ? fmaxf(fmaf(g2[n0 + lane], scG, sfG), 0.f) : -INFINITY;
    float m = gv;
#pragma unroll
    for (int o = 16; o; o >>= 1) m = fmaxf(m, __shfl_xor_sync(FULL, m, o));
    float ev = (lane < ONE_STEP) ? expf(gv - m) : 0.f;
    float s = ev;
#pragma unroll
    for (int o = 16; o; o >>= 1) s += __shfl_xor_sync(FULL, s, o);
    float inv = 1.0f / s;
    float sc4 = g_scale4[lane], sf4 = g_shift4[lane];
    float pooled = 0.f;
#pragma unroll
    for (int i = 0; i < ONE_STEP; i++) {
        float a = __shfl_sync(FULL, ev, i) * inv;
        float hv = fmaf(y4[(size_t)(n0 + i) * 32 + lane], sc4, sf4);
        pooled = fmaf(a, hv, pooled);
    }
    float logits[10];
#pragma unroll
    for (int j = 0; j < 10; j++) {
        float p = pooled * fcW[lane * 10 + j];
#pragma unroll
        for (int o = 16; o; o >>= 1) p += __shfl_xor_sync(FULL, p, o);
        logits[j] = p + fcb[j];
    }
    if (lane == 0) {
        float mx = logits[0];
#pragma unroll
        for (int j = 1; j < 10; j++) mx = fmaxf(mx, logits[j]);
        float ss = 0.f;
        float e[10];
#pragma unroll
        for (int j = 0; j < 10; j++) { e[j] = expf(logits[j] - mx); ss += e[j]; }
        float invs = 1.0f / ss;
#pragma unroll
        for (int j = 0; j < 10; j++) out[warp * 10 + j] = e[j] * invs;
    }
}

// ---------------- host orchestration ----------------
extern "C" void kernel_launch(void* const* d_in, const int* in_sizes, int n_in,
                              void* d_out, int out_size) {
    const float* x    = (const float*)d_in[0];
    const int*   ei   = (const int*)d_in[1];
    const float* W1   = (const float*)d_in[2];
    const float* b1   = (const float*)d_in[3];
    const float* bn1g = (const float*)d_in[4];
    const float* bn1b = (const float*)d_in[5];
    const float* W2   = (const float*)d_in[6];
    const float* b2   = (const float*)d_in[7];
    const float* bn2g = (const float*)d_in[8];
    const float* bn2b = (const float*)d_in[9];
    const float* W3   = (const float*)d_in[10];
    const float* b3   = (const float*)d_in[11];
    const float* bn3g = (const float*)d_in[12];
    const float* bn3b = (const float*)d_in[13];
    const float* W4   = (const float*)d_in[14];
    const float* b4   = (const float*)d_in[15];
    const float* bn4g = (const float*)d_in[16];
    const float* bn4b = (const float*)d_in[17];
    const float* gW1  = (const float*)d_in[18];
    const float* gb1  = (const float*)d_in[19];
    const float* gbn1g = (const float*)d_in[20];
    const float* gbn1b = (const float*)d_in[21];
    const float* gW2  = (const float*)d_in[22];
    const float* gb2  = (const float*)d_in[23];
    const float* gbn2g = (const float*)d_in[24];
    const float* gbn2b = (const float*)d_in[25];
    const float* fcW  = (const float*)d_in[26];
    const float* fcb  = (const float*)d_in[27];
    float* out = (float*)d_out;

    float *buf0, *buf1, *buf2;
    float *scA, *shA, *sc4, *sh4, *scG1, *shG1, *scG2, *shG2;
    cudaGetSymbolAddress((void**)&buf0, g_buf0);
    cudaGetSymbolAddress((void**)&buf1, g_buf1);
    cudaGetSymbolAddress((void**)&buf2, g_buf2);
    cudaGetSymbolAddress((void**)&scA, g_scaleA);
    cudaGetSymbolAddress((void**)&shA, g_shiftA);
    cudaGetSymbolAddress((void**)&sc4, g_scale4);
    cudaGetSymbolAddress((void**)&sh4, g_shift4);
    cudaGetSymbolAddress((void**)&scG1, g_scaleG1);
    cudaGetSymbolAddress((void**)&shG1, g_shiftG1);
    cudaGetSymbolAddress((void**)&scG2, g_scaleG2);
    cudaGetSymbolAddress((void**)&shG2, g_shiftG2);

    const int GRID = N_NODES / 128;  // 896
    const int EB = (N_EDGES + 255) / 256;
    const int SM_L1 = (2 * 128 * 20 + 2 * 128 * 20) * 4;                    // 40960
    const int SM_L2 = (2 * 128 * 20 + 2 * 128 * 20) * 4 + 2 * 128 * 4;      // 41984 (stats)
    const int SM_L3 = (2 * 128 * 20 + 2 * 64 * 20 + 2 * 256) * 4;           // 32768
    cudaFuncSetAttribute((const void*)mma_gemm_kernel<128, 128, 512, false, 0>,
                         cudaFuncAttributeMaxDynamicSharedMemorySize, SM_L1);
    cudaFuncSetAttribute((const void*)mma_gemm_kernel<256, 128, 128, false, 1>,
                         cudaFuncAttributeMaxDynamicSharedMemorySize, SM_L2);
    cudaFuncSetAttribute((const void*)mma_gemm_kernel<64, 64, 256, true, 0>,
                         cudaFuncAttributeMaxDynamicSharedMemorySize, SM_L3);

    // ---- CSR build + zero stats zones (once; shared by all layers) ----
    cnt_zero_kernel<<<NBLK, 256>>>();
    cnt_count_kernel<<<EB, 256>>>(ei);
    dis_kernel<<<NBLK, 256>>>();
    scan1_kernel<<<NBLK, 256>>>();
    scan2_kernel<<<1, 512>>>();
    scan3_kernel<<<NBLK, 256>>>();
    scatter_kernel<<<EB, 256>>>(ei);

    // ---- Layer 1 (512 -> 128): GEMM -> CSR agg (+bias+relu+stats z0) ----
    mma_gemm_kernel<128, 128, 512, false, 0><<<dim3(1, GRID), 256, SM_L1>>>(x, W1, nullptr, buf1, 0);
    csr_agg_kernel<128, false, true><<<1792, 256>>>(buf1, b1, buf0, 0);
    bn_finalize_kernel<<<1, 128>>>(bn1g, bn1b, 128, scA, shA, 0);

    // ---- Layer 2 (128 -> 256): CSR agg first (BN fused), GEMM + relu + stats z1 ----
    csr_agg_kernel<128, true, false><<<1792, 256>>>(buf0, nullptr, buf2, 0);
    mma_gemm_kernel<256, 128, 128, false, 1><<<dim3(2, GRID), 256, SM_L2>>>(buf2, W2, b2, buf0, 1);
    bn_finalize_kernel<<<1, 256>>>(bn2g, bn2b, 256, scA, shA, 1);

    // ---- Layer 3 (256 -> 64): GEMM (BN fused) -> CSR agg (+bias+relu+stats z2) ----
    mma_gemm_kernel<64, 64, 256, true, 0><<<dim3(1, GRID), 256, SM_L3>>>(buf0, W3, nullptr, buf1, 0);
    csr_agg_kernel<64, false, true><<<1792, 256>>>(buf1, b3, buf0, 2);
    bn_finalize_kernel<<<1, 64>>>(bn3g, bn3b, 64, scA, shA, 2);

    // ---- Layer 4 (64 -> 32): fp32 GEMM (BN fused) -> CSR agg (+stats z3) ----
    gemm_kernel<32, 2, true><<<dim3(1, GRID), 256>>>(buf0, W4, buf1, 64, 32);
    csr_agg_kernel<32, false, true><<<1792, 256>>>(buf1, b4, buf0, 3);
    bn_finalize_kernel<<<1, 32>>>(bn4g, bn4b, 32, sc4, sh4, 3);

    // ---- gate layer 1 (stats fused, z4) ----
    gate1_kernel<<<N_NODES / 256, 256>>>(buf0, gW1, gb1, buf1);
    bn_finalize_kernel<<<1, 16>>>(gbn1g, gbn1b, 16, scG1, shG1, 4);

    // ---- gate layer 2 (stats fused, z5) ----
    gate2_kernel<<<N_NODES / 256, 256>>>(buf1, gW2, gb2, buf2);
    bn_finalize_kernel<<<1, 32>>>(gbn2g, gbn2b, 1, scG2, shG2, 5);

    // ---- segment softmax pooling + FC + softmax ----
    pool_fc_kernel<<<(NGRAPH * 32 + 255) / 256, 256>>>(buf0, buf2, fcW, fcb, out);
}

// round 16
// speedup vs baseline: 1.0478x; 1.0478x over previous
#include <cuda_runtime.h>
#include <cuda_bf16.h>
#include <math.h>
#include <stdint.h>

#define N_NODES 114688
#define N_EDGES 917504
#define MAXC    256
#define BN_EPS  1e-5f
#define ONE_STEP 14
#define NGRAPH  (N_NODES / ONE_STEP)
#define NBLK    448              // N_NODES / 256

// ---------------- scratch (static device globals; no allocation) ----------------
__device__ __align__(16) float  g_buf0[(size_t)N_NODES * MAXC];
__device__ __align__(16) float  g_buf1[(size_t)N_NODES * MAXC];
__device__ __align__(16) float  g_buf2[(size_t)N_NODES * MAXC];
__device__ float  g_dis[N_NODES];
__device__ double g_sum[6 * MAXC], g_sumsq[6 * MAXC];   // zones: L1,L2,L3,L4,G1,G2
__device__ __align__(16) float g_scaleA[MAXC], g_shiftA[MAXC];
__device__ __align__(16) float g_scale4[32],  g_shift4[32];
__device__ __align__(16) float g_scaleG1[16], g_shiftG1[16];
__device__ __align__(16) float g_scaleG2[4],  g_shiftG2[4];
// CSR scratch
__device__ int g_cnt[N_NODES];
__device__ int g_rowptr[N_NODES + 1];
__device__ int g_cursor[N_NODES];
__device__ int g_ssrc[N_EDGES];
__device__ int g_bsum[NBLK];

__device__ __forceinline__ uint32_t pack_bf16x2(float a, float b) {
    uint32_t r;
    asm("cvt.rn.bf16x2.f32 %0, %1, %2;" : "=r"(r) : "f"(b), "f"(a));
    return r;
}
__device__ __forceinline__ void split2_bf16(float v0, float v1, uint32_t& h, uint32_t& l) {
    float h0 = __bfloat162float(__float2bfloat16(v0));
    float h1 = __bfloat162float(__float2bfloat16(v1));
    h = pack_bf16x2(h0, h1);
    l = pack_bf16x2(v0 - h0, v1 - h1);
}
__device__ __forceinline__ void mma_bf16(float* c, const uint32_t* a, uint32_t b0, uint32_t b1) {
    asm volatile(
        "mma.sync.aligned.m16n8k16.row.col.f32.bf16.bf16.f32 "
        "{%0,%1,%2,%3}, {%4,%5,%6,%7}, {%8,%9}, {%0,%1,%2,%3};"
        : "+f"(c[0]), "+f"(c[1]), "+f"(c[2]), "+f"(c[3])
        : "r"(a[0]), "r"(a[1]), "r"(a[2]), "r"(a[3]), "r"(b0), "r"(b1));
}

// ---------------- CSR build (+ stats-zone zeroing, dis fused into scan1) ----------------
__global__ void cnt_zero_kernel() {
    int i = blockIdx.x * 256 + threadIdx.x;
    if (i < N_NODES) g_cnt[i] = 0;
    if (blockIdx.x < 6) {
        int z = blockIdx.x * 256 + threadIdx.x;
        g_sum[z] = 0.0;
        g_sumsq[z] = 0.0;
    }
}
__global__ void cnt_count_kernel(const int* __restrict__ ei) {
    int e = blockIdx.x * 256 + threadIdx.x;
    if (e < N_EDGES) atomicAdd(&g_cnt[ei[N_EDGES + e]], 1);
}
__global__ void scan1_kernel() {
    __shared__ int sh[256];
    int tid = threadIdx.x;
    int i = blockIdx.x * 256 + tid;
    int v = g_cnt[i];
    g_dis[i] = rsqrtf((float)v + 1.0f);        // fused degree normalization
    sh[tid] = v;
    __syncthreads();
#pragma unroll
    for (int off = 1; off < 256; off <<= 1) {
        int t = (tid >= off) ? sh[tid - off] : 0;
        __syncthreads();
        sh[tid] += t;
        __syncthreads();
    }
    g_rowptr[i] = sh[tid] - v;
    if (tid == 255) g_bsum[blockIdx.x] = sh[255];
}
__global__ void scan2_kernel() {
    __shared__ int sh[512];
    int tid = threadIdx.x;
    int v = (tid < NBLK) ? g_bsum[tid] : 0;
    sh[tid] = v;
    __syncthreads();
#pragma unroll
    for (int off = 1; off < 512; off <<= 1) {
        int t = (tid >= off) ? sh[tid - off] : 0;
        __syncthreads();
        sh[tid] += t;
        __syncthreads();
    }
    if (tid < NBLK) g_bsum[tid] = sh[tid] - v;
}
__global__ void scan3_kernel() {
    int i = blockIdx.x * 256 + threadIdx.x;
    int r = g_rowptr[i] + g_bsum[blockIdx.x];
    g_rowptr[i] = r;
    g_cursor[i] = r;
    if (i == 0) g_rowptr[N_NODES] = N_EDGES;
}
__global__ void scatter_kernel(const int* __restrict__ ei) {
    int e = blockIdx.x * 256 + threadIdx.x;
    if (e < N_EDGES) {
        int dst = ei[N_EDGES + e];
        int pos = atomicAdd(&g_cursor[dst], 1);
        g_ssrc[pos] = ei[e];
    }
}

// ---------------- CSR aggregation ----------------
template<int C, bool AFFINE, bool COMBINE>
__global__ __launch_bounds__(256)
void csr_agg_kernel(const float* __restrict__ z, const float* __restrict__ b,
                    float* __restrict__ out, int zone) {
    const int c4n = C / 4;
    const int DPW = 32 / c4n;
    const int DPB = DPW * 8;
    int lane = threadIdx.x & 31, wid = threadIdx.x >> 5;
    int sub = lane / c4n, cc = lane % c4n;
    float4 bb = make_float4(0.f, 0.f, 0.f, 0.f), sc, sf;
    if (COMBINE) bb = ((const float4*)b)[cc];
    if (AFFINE) { sc = ((const float4*)g_scaleA)[cc]; sf = ((const float4*)g_shiftA)[cc]; }
    float s[4] = {0, 0, 0, 0}, q[4] = {0, 0, 0, 0};

    for (int d0 = blockIdx.x * DPB; d0 < N_NODES; d0 += gridDim.x * DPB) {
        int dst = d0 + wid * DPW + sub;
        float dd = g_dis[dst];
        int beg = g_rowptr[dst], end = g_rowptr[dst + 1];
        float4 vz = *((const float4*)(z + (size_t)dst * C) + cc);
        if (AFFINE) {
            vz.x = fmaf(vz.x, sc.x, sf.x);
            vz.y = fmaf(vz.y, sc.y, sf.y);
            vz.z = fmaf(vz.z, sc.z, sf.z);
            vz.w = fmaf(vz.w, sc.w, sf.w);
        }
        float ss = dd * dd;
        float4 acc = make_float4(vz.x * ss, vz.y * ss, vz.z * ss, vz.w * ss);
        int i = beg;
        for (; i + 3 < end; i += 4) {
            int s0 = g_ssrc[i], s1 = g_ssrc[i + 1], s2 = g_ssrc[i + 2], s3 = g_ssrc[i + 3];
            float n0 = g_dis[s0] * dd, n1 = g_dis[s1] * dd;
            float n2 = g_dis[s2] * dd, n3 = g_dis[s3] * dd;
            float4 v0 = *((const float4*)(z + (size_t)s0 * C) + cc);
            float4 v1 = *((const float4*)(z + (size_t)s1 * C) + cc);
            float4 v2 = *((const float4*)(z + (size_t)s2 * C) + cc);
            float4 v3 = *((const float4*)(z + (size_t)s3 * C) + cc);
            if (AFFINE) {
                v0.x = fmaf(v0.x, sc.x, sf.x); v0.y = fmaf(v0.y, sc.y, sf.y);
                v0.z = fmaf(v0.z, sc.z, sf.z); v0.w = fmaf(v0.w, sc.w, sf.w);
                v1.x = fmaf(v1.x, sc.x, sf.x); v1.y = fmaf(v1.y, sc.y, sf.y);
                v1.z = fmaf(v1.z, sc.z, sf.z); v1.w = fmaf(v1.w, sc.w, sf.w);
                v2.x = fmaf(v2.x, sc.x, sf.x); v2.y = fmaf(v2.y, sc.y, sf.y);
                v2.z = fmaf(v2.z, sc.z, sf.z); v2.w = fmaf(v2.w, sc.w, sf.w);
                v3.x = fmaf(v3.x, sc.x, sf.x); v3.y = fmaf(v3.y, sc.y, sf.y);
                v3.z = fmaf(v3.z, sc.z, sf.z); v3.w = fmaf(v3.w, sc.w, sf.w);
            }
            acc.x = fmaf(v0.x, n0, fmaf(v1.x, n1, fmaf(v2.x, n2, fmaf(v3.x, n3, acc.x))));
            acc.y = fmaf(v0.y, n0, fmaf(v1.y, n1, fmaf(v2.y, n2, fmaf(v3.y, n3, acc.y))));
            acc.z = fmaf(v0.z, n0, fmaf(v1.z, n1, fmaf(v2.z, n2, fmaf(v3.z, n3, acc.z))));
            acc.w = fmaf(v0.w, n0, fmaf(v1.w, n1, fmaf(v2.w, n2, fmaf(v3.w, n3, acc.w))));
        }
        for (; i < end; i++) {
            int s0 = g_ssrc[i];
            float n0 = g_dis[s0] * dd;
            float4 v0 = *((const float4*)(z + (size_t)s0 * C) + cc);
            if (AFFINE) {
                v0.x = fmaf(v0.x, sc.x, sf.x); v0.y = fmaf(v0.y, sc.y, sf.y);
                v0.z = fmaf(v0.z, sc.z, sf.z); v0.w = fmaf(v0.w, sc.w, sf.w);
            }
            acc.x = fmaf(v0.x, n0, acc.x);
            acc.y = fmaf(v0.y, n0, acc.y);
            acc.z = fmaf(v0.z, n0, acc.z);
            acc.w = fmaf(v0.w, n0, acc.w);
        }
        if (COMBINE) {
            acc.x = fmaxf(acc.x + bb.x, 0.f);
            acc.y = fmaxf(acc.y + bb.y, 0.f);
            acc.z = fmaxf(acc.z + bb.z, 0.f);
            acc.w = fmaxf(acc.w + bb.w, 0.f);
            s[0] += acc.x; q[0] += acc.x * acc.x;
            s[1] += acc.y; q[1] += acc.y * acc.y;
            s[2] += acc.z; q[2] += acc.z * acc.z;
            s[3] += acc.w; q[3] += acc.w * acc.w;
        }
        *((float4*)(out + (size_t)dst * C) + cc) = acc;
    }
    if (COMBINE) {
        __shared__ float csum[C], csq[C];
        for (int i = threadIdx.x; i < C; i += 256) { csum[i] = 0.f; csq[i] = 0.f; }
        __syncthreads();
#pragma unroll
        for (int j = 0; j < 4; j++) {
            atomicAdd(&csum[cc * 4 + j], s[j]);
            atomicAdd(&csq[cc * 4 + j],  q[j]);
        }
        __syncthreads();
        for (int i = threadIdx.x; i < C; i += 256) {
            atomicAdd(&g_sum[zone * MAXC + i],   (double)csum[i]);
            atomicAdd(&g_sumsq[zone * MAXC + i], (double)csq[i]);
        }
    }
}

// ---------------- 3xBF16 mma.sync GEMM (m16n8k16, split-at-store) — R13 exact ----------------
// EPI 0: out = z.  EPI 1: out = relu(z + bias).  (no stats in epilogue!)
template<int CO, int BN, int K, bool AFFINE, int EPI>
__global__ __launch_bounds__(256, 2)
void mma_gemm_kernel(const float* __restrict__ A, const float* __restrict__ W,
                     const float* __restrict__ bias, float* __restrict__ out) {
    const int ASTR = 20;
    const int BSTR = 20;
    const int AW = 128 * ASTR;
    const int BW = BN * BSTR;
    extern __shared__ uint32_t sm[];
    uint32_t* const Ah = sm;
    uint32_t* const Al = sm + AW;
    uint32_t* const Bh = sm + 2 * AW;
    uint32_t* const Bl = sm + 2 * AW + BW;
    float* const scs = (float*)(sm + 2 * AW + 2 * BW);
    float* const sfs = scs + K;

    const int tid = threadIdx.x;
    const int lane = tid & 31, wid = tid >> 5;
    const int warpM = wid & 3, warpN = wid >> 2;
    const int WN = BN / 2;
    const int NT = WN / 8;
    const int g = lane >> 2, kk = lane & 3;
    const int row0 = blockIdx.y * 128;
    const int col0 = blockIdx.x * BN;

    if (AFFINE) {
        for (int i = tid; i < K; i += 256) { scs[i] = g_scaleA[i]; sfs[i] = g_shiftA[i]; }
        __syncthreads();
    }

    float acc[2][NT][4];
#pragma unroll
    for (int t = 0; t < 2; t++)
#pragma unroll
        for (int j = 0; j < NT; j++)
#pragma unroll
            for (int q = 0; q < 4; q++) acc[t][j][q] = 0.f;

    const int NCH = K / 32;
    for (int ch = 0; ch < NCH; ch++) {
        const int k0 = ch * 32;
        if (ch) __syncthreads();
#pragma unroll
        for (int i = 0; i < 4; i++) {
            int f = tid + i * 256;
            int r = f >> 3;
            int kq = (f & 7) * 4;
            float4 v = *(const float4*)(A + (size_t)(row0 + r) * K + k0 + kq);
            if (AFFINE) {
                v.x = fmaf(v.x, scs[k0 + kq + 0], sfs[k0 + kq + 0]);
                v.y = fmaf(v.y, scs[k0 + kq + 1], sfs[k0 + kq + 1]);
                v.z = fmaf(v.z, scs[k0 + kq + 2], sfs[k0 + kq + 2]);
                v.w = fmaf(v.w, scs[k0 + kq + 3], sfs[k0 + kq + 3]);
            }
            uint32_t h0, l0, h1, l1;
            split2_bf16(v.x, v.y, h0, l0);
            split2_bf16(v.z, v.w, h1, l1);
            int p = kq >> 1;
            Ah[r * ASTR + p] = h0; Ah[r * ASTR + p + 1] = h1;
            Al[r * ASTR + p] = l0; Al[r * ASTR + p + 1] = l1;
        }
        const int NBT = BN / 64;
#pragma unroll
        for (int i = 0; i < NBT; i++) {
            int f = tid + i * 256;
            int pr = f & 15;
            int c = (f >> 4) * 4;
            const float* Wp = W + (size_t)(k0 + 2 * pr) * CO + col0 + c;
            float4 w0 = *(const float4*)Wp;
            float4 w1 = *(const float4*)(Wp + CO);
            uint32_t h, l;
            split2_bf16(w0.x, w1.x, h, l);
            Bh[(c + 0) * BSTR + pr] = h; Bl[(c + 0) * BSTR + pr] = l;
            split2_bf16(w0.y, w1.y, h, l);
            Bh[(c + 1) * BSTR + pr] = h; Bl[(c + 1) * BSTR + pr] = l;
            split2_bf16(w0.z, w1.z, h, l);
            Bh[(c + 2) * BSTR + pr] = h; Bl[(c + 2) * BSTR + pr] = l;
            split2_bf16(w0.w, w1.w, h, l);
            Bh[(c + 3) * BSTR + pr] = h; Bl[(c + 3) * BSTR + pr] = l;
        }
        __syncthreads();
#pragma unroll
        for (int ks = 0; ks < 2; ks++) {
            const int kp = ks * 8;
#pragma unroll
            for (int t = 0; t < 2; t++) {
                const int r = warpM * 32 + t * 16 + g;
                uint32_t ah[4], al[4];
                ah[0] = Ah[r * ASTR + kp + kk];
                ah[1] = Ah[(r + 8) * ASTR + kp + kk];
                ah[2] = Ah[r * ASTR + kp + kk + 4];
                ah[3] = Ah[(r + 8) * ASTR + kp + kk + 4];
                al[0] = Al[r * ASTR + kp + kk];
                al[1] = Al[(r + 8) * ASTR + kp + kk];
                al[2] = Al[r * ASTR + kp + kk + 4];
                al[3] = Al[(r + 8) * ASTR + kp + kk + 4];
#pragma unroll
                for (int j = 0; j < NT; j++) {
                    int n = warpN * WN + j * 8 + g;
                    uint32_t b0h = Bh[n * BSTR + kp + kk];
                    uint32_t b1h = Bh[n * BSTR + kp + kk + 4];
                    uint32_t b0l = Bl[n * BSTR + kp + kk];
                    uint32_t b1l = Bl[n * BSTR + kp + kk + 4];
                    mma_bf16(acc[t][j], ah, b0h, b1h);
                    mma_bf16(acc[t][j], al, b0h, b1h);
                    mma_bf16(acc[t][j], ah, b0l, b1l);
                }
            }
        }
    }

#pragma unroll
    for (int t = 0; t < 2; t++) {
        const int r = row0 + warpM * 32 + t * 16 + g;
#pragma unroll
        for (int j = 0; j < NT; j++) {
            const int c = col0 + warpN * WN + j * 8 + 2 * kk;
            float2 v1 = make_float2(acc[t][j][0], acc[t][j][1]);
            float2 v2 = make_float2(acc[t][j][2], acc[t][j][3]);
            if (EPI == 1) {
                float2 bb = *(const float2*)(bias + c);
                v1.x = fmaxf(v1.x + bb.x, 0.f);
                v1.y = fmaxf(v1.y + bb.y, 0.f);
                v2.x = fmaxf(v2.x + bb.x, 0.f);
                v2.y = fmaxf(v2.y + bb.y, 0.f);
            }
            *(float2*)(out + (size_t)r * CO + c) = v1;
            *(float2*)(out + (size_t)(r + 8) * CO + c) = v2;
        }
    }
}

// ---------------- fp32 GEMM (layer 4: 64 -> 32), writes z only ----------------
template<int BN_T, int TN_T, bool AFFINE>
__global__ __launch_bounds__(256, 2)
void gemm_kernel(const float* __restrict__ A, const float* __restrict__ W,
                 float* __restrict__ out, int K, int Co) {
    __shared__ float As[16][128];
    __shared__ float Ws[16][BN_T];
    __shared__ float sc_sh[256], sf_sh[256];
    int tid = threadIdx.x;
    int tx = tid & 15, ty = tid >> 4;
    int row0 = blockIdx.y * 128;
    int col0 = blockIdx.x * BN_T;
    if (AFFINE) {
        for (int i = tid; i < K; i += 256) { sc_sh[i] = g_scaleA[i]; sf_sh[i] = g_shiftA[i]; }
    }
    float acc[8][TN_T];
#pragma unroll
    for (int i = 0; i < 8; i++)
#pragma unroll
        for (int j = 0; j < TN_T; j++) acc[i][j] = 0.f;
    if (AFFINE) __syncthreads();
    for (int k0 = 0; k0 < K; k0 += 16) {
#pragma unroll
        for (int i = 0; i < 2; i++) {
            int f = tid * 2 + i;
            int r = f >> 2;
            int kq = (f & 3) * 4;
            float4 v = *(const float4*)(A + (size_t)(row0 + r) * K + k0 + kq);
            if (AFFINE) {
                v.x = fmaf(v.x, sc_sh[k0 + kq + 0], sf_sh[k0 + kq + 0]);
                v.y = fmaf(v.y, sc_sh[k0 + kq + 1], sf_sh[k0 + kq + 1]);
                v.z = fmaf(v.z, sc_sh[k0 + kq + 2], sf_sh[k0 + kq + 2]);
                v.w = fmaf(v.w, sc_sh[k0 + kq + 3], sf_sh[k0 + kq + 3]);
            }
            As[kq + 0][r] = v.x; As[kq + 1][r] = v.y;
            As[kq + 2][r] = v.z; As[kq + 3][r] = v.w;
        }
        {
            const int NF4 = 16 * BN_T / 4;
#pragma unroll
            for (int i = 0; i < (NF4 + 255) / 256; i++) {
                int f = tid + i * 256;
                if ((NF4 % 256 == 0) || f < NF4) {
                    int k = f / (BN_T / 4);
                    int c = (f % (BN_T / 4)) * 4;
                    float4 v = *(const float4*)(W + (size_t)(k0 + k) * Co + col0 + c);
                    Ws[k][c + 0] = v.x; Ws[k][c + 1] = v.y;
                    Ws[k][c + 2] = v.z; Ws[k][c + 3] = v.w;
                }
            }
        }
        __syncthreads();
#pragma unroll
        for (int kk = 0; kk < 16; kk++) {
            float a[8], w[TN_T];
            float4 a0 = *(const float4*)&As[kk][ty * 4];
            float4 a1 = *(const float4*)&As[kk][64 + ty * 4];
            a[0] = a0.x; a[1] = a0.y; a[2] = a0.z; a[3] = a0.w;
            a[4] = a1.x; a[5] = a1.y; a[6] = a1.z; a[7] = a1.w;
            if (TN_T == 4) {
                float4 w0 = *(const float4*)&Ws[kk][tx * 4];
                w[0] = w0.x; w[1] = w0.y; w[2] = w0.z; w[3] = w0.w;
            } else {
                float2 w0 = *(const float2*)&Ws[kk][tx * 2];
                w[0] = w0.x; w[1] = w0.y;
            }
#pragma unroll
            for (int i = 0; i < 8; i++)
#pragma unroll
                for (int j = 0; j < TN_T; j++) acc[i][j] = fmaf(a[i], w[j], acc[i][j]);
        }
        __syncthreads();
    }
#pragma unroll
    for (int i = 0; i < 8; i++) {
        int r = row0 + ((i < 4) ? (ty * 4 + i) : (64 + ty * 4 + i - 4));
        if (TN_T >= 4) {
            int c = col0 + tx * 4;
            *(float4*)(out + (size_t)r * Co + c) =
                make_float4(acc[i][0], acc[i][1], acc[i][2], acc[i][3]);
        } else {
            int c = col0 + tx * 2;
            *(float2*)(out + (size_t)r * Co + c) = make_float2(acc[i][0], acc[i][1]);
        }
    }
}

// ---------------- BN stats helpers ----------------
template<int C>
__global__ void stats_only_kernel(const float* __restrict__ y, int zone) {
    const int c4n = C / 4;
    const int ROWS = 256 / c4n;
    int cc = threadIdx.x % c4n;
    int rg = threadIdx.x / c4n;
    float s[4] = {0, 0, 0, 0}, q[4] = {0, 0, 0, 0};
    for (int r = blockIdx.x * ROWS + rg; r < N_NODES; r += gridDim.x * ROWS) {
        float4 v = *((const float4*)(y + (size_t)r * C) + cc);
        s[0] += v.x; q[0] += v.x * v.x;
        s[1] += v.y; q[1] += v.y * v.y;
        s[2] += v.z; q[2] += v.z * v.z;
        s[3] += v.w; q[3] += v.w * v.w;
    }
    __shared__ float shs[256 * 4], shq[256 * 4];
#pragma unroll
    for (int j = 0; j < 4; j++) { shs[threadIdx.x * 4 + j] = s[j]; shq[threadIdx.x * 4 + j] = q[j]; }
    __syncthreads();
    if (rg == 0) {
#pragma unroll 1
        for (int g = 1; g < ROWS; g++) {
            int base = (g * c4n + cc) * 4;
#pragma unroll
            for (int j = 0; j < 4; j++) { s[j] += shs[base + j]; q[j] += shq[base + j]; }
        }
#pragma unroll
        for (int j = 0; j < 4; j++) {
            atomicAdd(&g_sum[zone * MAXC + cc * 4 + j],   (double)s[j]);
            atomicAdd(&g_sumsq[zone * MAXC + cc * 4 + j], (double)q[j]);
        }
    }
}

__global__ void bn_finalize_kernel(const float* __restrict__ gam, const float* __restrict__ bet,
                                   int C, float* __restrict__ oS, float* __restrict__ oH,
                                   int zone) {
    int c = threadIdx.x;
    if (c >= C) return;
    double mean = g_sum[zone * MAXC + c] / (double)N_NODES;
    double var = g_sumsq[zone * MAXC + c] / (double)N_NODES - mean * mean;
    double sc = (double)gam[c] / sqrt(var + (double)BN_EPS);
    oS[c] = (float)sc;
    oH[c] = bet[c] - (float)(mean * sc);
}

// ---------------- gate network (stats fused) ----------------
__global__ void gate1_kernel(const float* __restrict__ y4, const float* __restrict__ gW1,
                             const float* __restrict__ gb1, float* __restrict__ outz) {
    __shared__ float w[32 * 16];
    __shared__ float bb[16], sc[32], sf[32];
    __shared__ float csum[16], csq[16];
    int tid = threadIdx.x;
    int lane = tid & 31;
    for (int i = tid; i < 512; i += 256) w[i] = gW1[i];
    if (tid < 16) { bb[tid] = gb1[tid]; csum[tid] = 0.f; csq[tid] = 0.f; }
    if (tid < 32) { sc[tid] = g_scale4[tid]; sf[tid] = g_shift4[tid]; }
    __syncthreads();
    int row = blockIdx.x * 256 + tid;
    float h[32];
#pragma unroll
    for (int k4 = 0; k4 < 8; k4++) {
        float4 v = *((const float4*)(y4 + (size_t)row * 32) + k4);
        h[k4 * 4 + 0] = fmaf(v.x, sc[k4 * 4 + 0], sf[k4 * 4 + 0]);
        h[k4 * 4 + 1] = fmaf(v.y, sc[k4 * 4 + 1], sf[k4 * 4 + 1]);
        h[k4 * 4 + 2] = fmaf(v.z, sc[k4 * 4 + 2], sf[k4 * 4 + 2]);
        h[k4 * 4 + 3] = fmaf(v.w, sc[k4 * 4 + 3], sf[k4 * 4 + 3]);
    }
    float acc[16];
#pragma unroll
    for (int j = 0; j < 16; j++) acc[j] = bb[j];
#pragma unroll
    for (int k = 0; k < 32; k++)
#pragma unroll
        for (int j = 0; j < 16; j++) acc[j] = fmaf(h[k], w[k * 16 + j], acc[j]);
#pragma unroll
    for (int j4 = 0; j4 < 4; j4++)
        *((float4*)(outz + (size_t)row * 16) + j4) =
            make_float4(acc[j4 * 4], acc[j4 * 4 + 1], acc[j4 * 4 + 2], acc[j4 * 4 + 3]);
#pragma unroll
    for (int j = 0; j < 16; j++) {
        float sv = acc[j], qv = acc[j] * acc[j];
#pragma unroll
        for (int o = 16; o; o >>= 1) {
            sv += __shfl_xor_sync(0xffffffffu, sv, o);
            qv += __shfl_xor_sync(0xffffffffu, qv, o);
        }
        if (lane == 0) { atomicAdd(&csum[j], sv); atomicAdd(&csq[j], qv); }
    }
    __syncthreads();
    if (tid < 16) {
        atomicAdd(&g_sum[4 * MAXC + tid],   (double)csum[tid]);
        atomicAdd(&g_sumsq[4 * MAXC + tid], (double)csq[tid]);
    }
}

__global__ void gate2_kernel(const float* __restrict__ z, const float* __restrict__ gW2,
                             const float* __restrict__ gb2, float* __restrict__ out) {
    __shared__ float w[16], sc[16], sf[16], b0;
    __shared__ float ws[8], wq[8];
    int tid = threadIdx.x;
    int lane = tid & 31, wid = tid >> 5;
    if (tid < 16) { w[tid] = gW2[tid]; sc[tid] = g_scaleG1[tid]; sf[tid] = g_shiftG1[tid]; }
    if (tid == 0) b0 = gb2[0];
    __syncthreads();
    int row = blockIdx.x * 256 + tid;
    float acc = b0;
#pragma unroll
    for (int k4 = 0; k4 < 4; k4++) {
        float4 v = *((const float4*)(z + (size_t)row * 16) + k4);
        acc = fmaf(fmaxf(fmaf(v.x, sc[k4 * 4 + 0], sf[k4 * 4 + 0]), 0.f), w[k4 * 4 + 0], acc);
        acc = fmaf(fmaxf(fmaf(v.y, sc[k4 * 4 + 1], sf[k4 * 4 + 1]), 0.f), w[k4 * 4 + 1], acc);
        acc = fmaf(fmaxf(fmaf(v.z, sc[k4 * 4 + 2], sf[k4 * 4 + 2]), 0.f), w[k4 * 4 + 2], acc);
        acc = fmaf(fmaxf(fmaf(v.w, sc[k4 * 4 + 3], sf[k4 * 4 + 3]), 0.f), w[k4 * 4 + 3], acc);
    }
    out[row] = acc;
    float sv = acc, qv = acc * acc;
#pragma unroll
    for (int o = 16; o; o >>= 1) {
        sv += __shfl_xor_sync(0xffffffffu, sv, o);
        qv += __shfl_xor_sync(0xffffffffu, qv, o);
    }
    if (lane == 0) { ws[wid] = sv; wq[wid] = qv; }
    __syncthreads();
    if (tid == 0) {
        float ts = 0.f, tq = 0.f;
#pragma unroll
        for (int i = 0; i < 8; i++) { ts += ws[i]; tq += wq[i]; }
        atomicAdd(&g_sum[5 * MAXC],   (double)ts);
        atomicAdd(&g_sumsq[5 * MAXC], (double)tq);
    }
}

// ---------------- pooling + FC + softmax ----------------
__global__ void pool_fc_kernel(const float* __restrict__ y4, const float* __restrict__ g2,
                               const float* __restrict__ fcW, const float* __restrict__ fcb,
                               float* __restrict__ out) {
    int warp = (blockIdx.x * blockDim.x + threadIdx.x) >> 5;
    int lane = threadIdx.x & 31;
    if (warp >= NGRAPH) return;
    int n0 = warp * ONE_STEP;
    const unsigned FULL = 0xffffffffu;
    float scG = g_scaleG2[0], sfG = g_shiftG2[0];
    float gv = (lane < ONE_STEP) ? fmaxf(fmaf(g2[n0 + lane], scG, sfG), 0.f) : -INFINITY;
    float m = gv;
#pragma unroll
    for (int o = 16; o; o >>= 1) m = fmaxf(m, __shfl_xor_sync(FULL, m, o));
    float ev = (lane < ONE_STEP) ? expf(gv - m) : 0.f;
    float s = ev;
#pragma unroll
    for (int o = 16; o; o >>= 1) s += __shfl_xor_sync(FULL, s, o);
    float inv = 1.0f / s;
    float sc4 = g_scale4[lane], sf4 = g_shift4[lane];
    float pooled = 0.f;
#pragma unroll
    for (int i = 0; i < ONE_STEP; i++) {
        float a = __shfl_sync(FULL, ev, i) * inv;
        float hv = fmaf(y4[(size_t)(n0 + i) * 32 + lane], sc4, sf4);
        pooled = fmaf(a, hv, pooled);
    }
    float logits[10];
#pragma unroll
    for (int j = 0; j < 10; j++) {
        float p = pooled * fcW[lane * 10 + j];
#pragma unroll
        for (int o = 16; o; o >>= 1) p += __shfl_xor_sync(FULL, p, o);
        logits[j] = p + fcb[j];
    }
    if (lane == 0) {
        float mx = logits[0];
#pragma unroll
        for (int j = 1; j < 10; j++) mx = fmaxf(mx, logits[j]);
        float ss = 0.f;
        float e[10];
#pragma unroll
        for (int j = 0; j < 10; j++) { e[j] = expf(logits[j] - mx); ss += e[j]; }
        float invs = 1.0f / ss;
#pragma unroll
        for (int j = 0; j < 10; j++) out[warp * 10 + j] = e[j] * invs;
    }
}

// ---------------- host orchestration ----------------
extern "C" void kernel_launch(void* const* d_in, const int* in_sizes, int n_in,
                              void* d_out, int out_size) {
    const float* x    = (const float*)d_in[0];
    const int*   ei   = (const int*)d_in[1];
    const float* W1   = (const float*)d_in[2];
    const float* b1   = (const float*)d_in[3];
    const float* bn1g = (const float*)d_in[4];
    const float* bn1b = (const float*)d_in[5];
    const float* W2   = (const float*)d_in[6];
    const float* b2   = (const float*)d_in[7];
    const float* bn2g = (const float*)d_in[8];
    const float* bn2b = (const float*)d_in[9];
    const float* W3   = (const float*)d_in[10];
    const float* b3   = (const float*)d_in[11];
    const float* bn3g = (const float*)d_in[12];
    const float* bn3b = (const float*)d_in[13];
    const float* W4   = (const float*)d_in[14];
    const float* b4   = (const float*)d_in[15];
    const float* bn4g = (const float*)d_in[16];
    const float* bn4b = (const float*)d_in[17];
    const float* gW1  = (const float*)d_in[18];
    const float* gb1  = (const float*)d_in[19];
    const float* gbn1g = (const float*)d_in[20];
    const float* gbn1b = (const float*)d_in[21];
    const float* gW2  = (const float*)d_in[22];
    const float* gb2  = (const float*)d_in[23];
    const float* gbn2g = (const float*)d_in[24];
    const float* gbn2b = (const float*)d_in[25];
    const float* fcW  = (const float*)d_in[26];
    const float* fcb  = (const float*)d_in[27];
    float* out = (float*)d_out;

    float *buf0, *buf1, *buf2;
    float *scA, *shA, *sc4, *sh4, *scG1, *shG1, *scG2, *shG2;
    cudaGetSymbolAddress((void**)&buf0, g_buf0);
    cudaGetSymbolAddress((void**)&buf1, g_buf1);
    cudaGetSymbolAddress((void**)&buf2, g_buf2);
    cudaGetSymbolAddress((void**)&scA, g_scaleA);
    cudaGetSymbolAddress((void**)&shA, g_shiftA);
    cudaGetSymbolAddress((void**)&sc4, g_scale4);
    cudaGetSymbolAddress((void**)&sh4, g_shift4);
    cudaGetSymbolAddress((void**)&scG1, g_scaleG1);
    cudaGetSymbolAddress((void**)&shG1, g_shiftG1);
    cudaGetSymbolAddress((void**)&scG2, g_scaleG2);
    cudaGetSymbolAddress((void**)&shG2, g_shiftG2);

    const int GRID = N_NODES / 128;  // 896
    const int EB = (N_EDGES + 255) / 256;
    const int SM_L1 = (2 * 128 * 20 + 2 * 128 * 20) * 4;             // 40960
    const int SM_L2 = (2 * 128 * 20 + 2 * 128 * 20) * 4;             // 40960
    const int SM_L3 = (2 * 128 * 20 + 2 * 64 * 20 + 2 * 256) * 4;    // 32768
    cudaFuncSetAttribute((const void*)mma_gemm_kernel<128, 128, 512, false, 0>,
                         cudaFuncAttributeMaxDynamicSharedMemorySize, SM_L1);
    cudaFuncSetAttribute((const void*)mma_gemm_kernel<256, 128, 128, false, 1>,
                         cudaFuncAttributeMaxDynamicSharedMemorySize, SM_L2);
    cudaFuncSetAttribute((const void*)mma_gemm_kernel<64, 64, 256, true, 0>,
                         cudaFuncAttributeMaxDynamicSharedMemorySize, SM_L3);

    // ---- CSR build + zero stats zones (dis fused into scan1) ----
    cnt_zero_kernel<<<NBLK, 256>>>();
    cnt_count_kernel<<<EB, 256>>>(ei);
    scan1_kernel<<<NBLK, 256>>>();
    scan2_kernel<<<1, 512>>>();
    scan3_kernel<<<NBLK, 256>>>();
    scatter_kernel<<<EB, 256>>>(ei);

    // ---- Layer 1 (512 -> 128): GEMM -> CSR agg (+bias+relu+stats z0) ----
    mma_gemm_kernel<128, 128, 512, false, 0><<<dim3(1, GRID), 256, SM_L1>>>(x, W1, nullptr, buf1);
    csr_agg_kernel<128, false, true><<<1792, 256>>>(buf1, b1, buf0, 0);
    bn_finalize_kernel<<<1, 128>>>(bn1g, bn1b, 128, scA, shA, 0);

    // ---- Layer 2 (128 -> 256): CSR agg first (BN fused), GEMM + relu, stats pass z1 ----
    csr_agg_kernel<128, true, false><<<1792, 256>>>(buf0, nullptr, buf2, 0);
    mma_gemm_kernel<256, 128, 128, false, 1><<<dim3(2, GRID), 256, SM_L2>>>(buf2, W2, b2, buf0);
    stats_only_kernel<256><<<512, 256>>>(buf0, 1);
    bn_finalize_kernel<<<1, 256>>>(bn2g, bn2b, 256, scA, shA, 1);

    // ---- Layer 3 (256 -> 64): GEMM (BN fused) -> CSR agg (+bias+relu+stats z2) ----
    mma_gemm_kernel<64, 64, 256, true, 0><<<dim3(1, GRID), 256, SM_L3>>>(buf0, W3, nullptr, buf1);
    csr_agg_kernel<64, false, true><<<1792, 256>>>(buf1, b3, buf0, 2);
    bn_finalize_kernel<<<1, 64>>>(bn3g, bn3b, 64, scA, shA, 2);

    // ---- Layer 4 (64 -> 32): fp32 GEMM (BN fused) -> CSR agg (+stats z3) ----
    gemm_kernel<32, 2, true><<<dim3(1, GRID), 256>>>(buf0, W4, buf1, 64, 32);
    csr_agg_kernel<32, false, true><<<1792, 256>>>(buf1, b4, buf0, 3);
    bn_finalize_kernel<<<1, 32>>>(bn4g, bn4b, 32, sc4, sh4, 3);

    // ---- gate layer 1 (stats fused, z4) ----
    gate1_kernel<<<N_NODES / 256, 256>>>(buf0, gW1, gb1, buf1);
    bn_finalize_kernel<<<1, 16>>>(gbn1g, gbn1b, 16, scG1, shG1, 4);

    // ---- gate layer 2 (stats fused, z5) ----
    gate2_kernel<<<N_NODES / 256, 256>>>(buf1, gW2, gb2, buf2);
    bn_finalize_kernel<<<1, 32>>>(gbn2g, gbn2b, 1, scG2, shG2, 5);

    // ---- segment softmax pooling + FC + softmax ----
    pool_fc_kernel<<<(NGRAPH * 32 + 255) / 256, 256>>>(buf0, buf2, fcW, fcb, out);
}

// round 17
// speedup vs baseline: 1.0483x; 1.0004x over previous
#include <cuda_runtime.h>
#include <cuda_bf16.h>
#include <math.h>
#include <stdint.h>

#define N_NODES 114688
#define N_EDGES 917504
#define MAXC    256
#define BN_EPS  1e-5f
#define ONE_STEP 14
#define NGRAPH  (N_NODES / ONE_STEP)
#define NBLK    448              // N_NODES / 256

// ---------------- scratch (static device globals; no allocation) ----------------
__device__ __align__(16) float  g_buf0[(size_t)N_NODES * MAXC];
__device__ __align__(16) float  g_buf1[(size_t)N_NODES * MAXC];
__device__ __align__(16) float  g_buf2[(size_t)N_NODES * MAXC];
__device__ float  g_dis[N_NODES];
__device__ double g_sum[6 * MAXC], g_sumsq[6 * MAXC];   // zones: L1,L2,L3,L4,G1,G2
__device__ __align__(16) float g_scaleA[MAXC], g_shiftA[MAXC];
__device__ __align__(16) float g_scale4[32],  g_shift4[32];
__device__ __align__(16) float g_scaleG1[16], g_shiftG1[16];
__device__ __align__(16) float g_scaleG2[4],  g_shiftG2[4];
// CSR scratch
__device__ int   g_cnt[N_NODES];
__device__ int   g_rowptr[N_NODES + 1];
__device__ int   g_cursor[N_NODES];
__device__ int   g_ssrc[N_EDGES];
__device__ float g_sw[N_EDGES];          // dis[src] per CSR slot
__device__ int   g_bsum[NBLK];

__device__ __forceinline__ uint32_t pack_bf16x2(float a, float b) {
    uint32_t r;
    asm("cvt.rn.bf16x2.f32 %0, %1, %2;" : "=r"(r) : "f"(b), "f"(a));
    return r;
}
__device__ __forceinline__ void split2_bf16(float v0, float v1, uint32_t& h, uint32_t& l) {
    float h0 = __bfloat162float(__float2bfloat16(v0));
    float h1 = __bfloat162float(__float2bfloat16(v1));
    h = pack_bf16x2(h0, h1);
    l = pack_bf16x2(v0 - h0, v1 - h1);
}
__device__ __forceinline__ void mma_bf16(float* c, const uint32_t* a, uint32_t b0, uint32_t b1) {
    asm volatile(
        "mma.sync.aligned.m16n8k16.row.col.f32.bf16.bf16.f32 "
        "{%0,%1,%2,%3}, {%4,%5,%6,%7}, {%8,%9}, {%0,%1,%2,%3};"
        : "+f"(c[0]), "+f"(c[1]), "+f"(c[2]), "+f"(c[3])
        : "r"(a[0]), "r"(a[1]), "r"(a[2]), "r"(a[3]), "r"(b0), "r"(b1));
}

// ---------------- CSR build (+ stats-zone zeroing, dis fused into scan1) ----------------
__global__ void cnt_zero_kernel() {
    int i = blockIdx.x * 256 + threadIdx.x;
    if (i < N_NODES) g_cnt[i] = 0;
    if (blockIdx.x < 6) {
        int z = blockIdx.x * 256 + threadIdx.x;
        g_sum[z] = 0.0;
        g_sumsq[z] = 0.0;
    }
}
__global__ void cnt_count_kernel(const int* __restrict__ ei) {
    int e = blockIdx.x * 256 + threadIdx.x;
    if (e < N_EDGES) atomicAdd(&g_cnt[ei[N_EDGES + e]], 1);
}
__global__ void scan1_kernel() {
    __shared__ int sh[256];
    int tid = threadIdx.x;
    int i = blockIdx.x * 256 + tid;
    int v = g_cnt[i];
    g_dis[i] = rsqrtf((float)v + 1.0f);
    sh[tid] = v;
    __syncthreads();
#pragma unroll
    for (int off = 1; off < 256; off <<= 1) {
        int t = (tid >= off) ? sh[tid - off] : 0;
        __syncthreads();
        sh[tid] += t;
        __syncthreads();
    }
    g_rowptr[i] = sh[tid] - v;
    if (tid == 255) g_bsum[blockIdx.x] = sh[255];
}
__global__ void scan2_kernel() {
    __shared__ int sh[512];
    int tid = threadIdx.x;
    int v = (tid < NBLK) ? g_bsum[tid] : 0;
    sh[tid] = v;
    __syncthreads();
#pragma unroll
    for (int off = 1; off < 512; off <<= 1) {
        int t = (tid >= off) ? sh[tid - off] : 0;
        __syncthreads();
        sh[tid] += t;
        __syncthreads();
    }
    if (tid < NBLK) g_bsum[tid] = sh[tid] - v;
}
__global__ void scan3_kernel() {
    int i = blockIdx.x * 256 + threadIdx.x;
    int r = g_rowptr[i] + g_bsum[blockIdx.x];
    g_rowptr[i] = r;
    g_cursor[i] = r;
    if (i == 0) g_rowptr[N_NODES] = N_EDGES;
}
__global__ void scatter_kernel(const int* __restrict__ ei) {
    int e = blockIdx.x * 256 + threadIdx.x;
    if (e < N_EDGES) {
        int src = ei[e];
        int dst = ei[N_EDGES + e];
        int pos = atomicAdd(&g_cursor[dst], 1);
        g_ssrc[pos] = src;
        g_sw[pos] = g_dis[src];
    }
}

// ---------------- CSR aggregation (sequential edge weights, MLP 8) ----------------
template<int C, bool AFFINE, bool COMBINE>
__global__ __launch_bounds__(256)
void csr_agg_kernel(const float* __restrict__ z, const float* __restrict__ b,
                    float* __restrict__ out, int zone) {
    const int c4n = C / 4;
    const int DPW = 32 / c4n;
    const int DPB = DPW * 8;
    int lane = threadIdx.x & 31, wid = threadIdx.x >> 5;
    int sub = lane / c4n, cc = lane % c4n;
    float4 bb = make_float4(0.f, 0.f, 0.f, 0.f), sc, sf;
    if (COMBINE) bb = ((const float4*)b)[cc];
    if (AFFINE) { sc = ((const float4*)g_scaleA)[cc]; sf = ((const float4*)g_shiftA)[cc]; }
    float s[4] = {0, 0, 0, 0}, q[4] = {0, 0, 0, 0};

    for (int d0 = blockIdx.x * DPB; d0 < N_NODES; d0 += gridDim.x * DPB) {
        int dst = d0 + wid * DPW + sub;
        float dd = g_dis[dst];
        int beg = g_rowptr[dst], end = g_rowptr[dst + 1];
        float4 vz = *((const float4*)(z + (size_t)dst * C) + cc);
        if (AFFINE) {
            vz.x = fmaf(vz.x, sc.x, sf.x);
            vz.y = fmaf(vz.y, sc.y, sf.y);
            vz.z = fmaf(vz.z, sc.z, sf.z);
            vz.w = fmaf(vz.w, sc.w, sf.w);
        }
        float ss = dd * dd;
        float4 acc = make_float4(vz.x * ss, vz.y * ss, vz.z * ss, vz.w * ss);
        int i = beg;
        // unroll 8: MLP 8 on the z gathers; weights come from sequential g_sw
        for (; i + 7 < end; i += 8) {
            int   sx[8];
            float nw[8];
            float4 vv[8];
#pragma unroll
            for (int u = 0; u < 8; u++) { sx[u] = g_ssrc[i + u]; nw[u] = g_sw[i + u] * dd; }
#pragma unroll
            for (int u = 0; u < 8; u++) vv[u] = *((const float4*)(z + (size_t)sx[u] * C) + cc);
#pragma unroll
            for (int u = 0; u < 8; u++) {
                if (AFFINE) {
                    vv[u].x = fmaf(vv[u].x, sc.x, sf.x);
                    vv[u].y = fmaf(vv[u].y, sc.y, sf.y);
                    vv[u].z = fmaf(vv[u].z, sc.z, sf.z);
                    vv[u].w = fmaf(vv[u].w, sc.w, sf.w);
                }
                acc.x = fmaf(vv[u].x, nw[u], acc.x);
                acc.y = fmaf(vv[u].y, nw[u], acc.y);
                acc.z = fmaf(vv[u].z, nw[u], acc.z);
                acc.w = fmaf(vv[u].w, nw[u], acc.w);
            }
        }
        for (; i + 3 < end; i += 4) {
            int   sx[4];
            float nw[4];
            float4 vv[4];
#pragma unroll
            for (int u = 0; u < 4; u++) { sx[u] = g_ssrc[i + u]; nw[u] = g_sw[i + u] * dd; }
#pragma unroll
            for (int u = 0; u < 4; u++) vv[u] = *((const float4*)(z + (size_t)sx[u] * C) + cc);
#pragma unroll
            for (int u = 0; u < 4; u++) {
                if (AFFINE) {
                    vv[u].x = fmaf(vv[u].x, sc.x, sf.x);
                    vv[u].y = fmaf(vv[u].y, sc.y, sf.y);
                    vv[u].z = fmaf(vv[u].z, sc.z, sf.z);
                    vv[u].w = fmaf(vv[u].w, sc.w, sf.w);
                }
                acc.x = fmaf(vv[u].x, nw[u], acc.x);
                acc.y = fmaf(vv[u].y, nw[u], acc.y);
                acc.z = fmaf(vv[u].z, nw[u], acc.z);
                acc.w = fmaf(vv[u].w, nw[u], acc.w);
            }
        }
        for (; i < end; i++) {
            int s0 = g_ssrc[i];
            float n0 = g_sw[i] * dd;
            float4 v0 = *((const float4*)(z + (size_t)s0 * C) + cc);
            if (AFFINE) {
                v0.x = fmaf(v0.x, sc.x, sf.x); v0.y = fmaf(v0.y, sc.y, sf.y);
                v0.z = fmaf(v0.z, sc.z, sf.z); v0.w = fmaf(v0.w, sc.w, sf.w);
            }
            acc.x = fmaf(v0.x, n0, acc.x);
            acc.y = fmaf(v0.y, n0, acc.y);
            acc.z = fmaf(v0.z, n0, acc.z);
            acc.w = fmaf(v0.w, n0, acc.w);
        }
        if (COMBINE) {
            acc.x = fmaxf(acc.x + bb.x, 0.f);
            acc.y = fmaxf(acc.y + bb.y, 0.f);
            acc.z = fmaxf(acc.z + bb.z, 0.f);
            acc.w = fmaxf(acc.w + bb.w, 0.f);
            s[0] += acc.x; q[0] += acc.x * acc.x;
            s[1] += acc.y; q[1] += acc.y * acc.y;
            s[2] += acc.z; q[2] += acc.z * acc.z;
            s[3] += acc.w; q[3] += acc.w * acc.w;
        }
        *((float4*)(out + (size_t)dst * C) + cc) = acc;
    }
    if (COMBINE) {
        __shared__ float csum[C], csq[C];
        for (int i = threadIdx.x; i < C; i += 256) { csum[i] = 0.f; csq[i] = 0.f; }
        __syncthreads();
#pragma unroll
        for (int j = 0; j < 4; j++) {
            atomicAdd(&csum[cc * 4 + j], s[j]);
            atomicAdd(&csq[cc * 4 + j],  q[j]);
        }
        __syncthreads();
        for (int i = threadIdx.x; i < C; i += 256) {
            atomicAdd(&g_sum[zone * MAXC + i],   (double)csum[i]);
            atomicAdd(&g_sumsq[zone * MAXC + i], (double)csq[i]);
        }
    }
}

// ---------------- 3xBF16 mma.sync GEMM (m16n8k16, split-at-store) — R13 exact ----------------
template<int CO, int BN, int K, bool AFFINE, int EPI>
__global__ __launch_bounds__(256, 2)
void mma_gemm_kernel(const float* __restrict__ A, const float* __restrict__ W,
                     const float* __restrict__ bias, float* __restrict__ out) {
    const int ASTR = 20;
    const int BSTR = 20;
    const int AW = 128 * ASTR;
    const int BW = BN * BSTR;
    extern __shared__ uint32_t sm[];
    uint32_t* const Ah = sm;
    uint32_t* const Al = sm + AW;
    uint32_t* const Bh = sm + 2 * AW;
    uint32_t* const Bl = sm + 2 * AW + BW;
    float* const scs = (float*)(sm + 2 * AW + 2 * BW);
    float* const sfs = scs + K;

    const int tid = threadIdx.x;
    const int lane = tid & 31, wid = tid >> 5;
    const int warpM = wid & 3, warpN = wid >> 2;
    const int WN = BN / 2;
    const int NT = WN / 8;
    const int g = lane >> 2, kk = lane & 3;
    const int row0 = blockIdx.y * 128;
    const int col0 = blockIdx.x * BN;

    if (AFFINE) {
        for (int i = tid; i < K; i += 256) { scs[i] = g_scaleA[i]; sfs[i] = g_shiftA[i]; }
        __syncthreads();
    }

    float acc[2][NT][4];
#pragma unroll
    for (int t = 0; t < 2; t++)
#pragma unroll
        for (int j = 0; j < NT; j++)
#pragma unroll
            for (int q = 0; q < 4; q++) acc[t][j][q] = 0.f;

    const int NCH = K / 32;
    for (int ch = 0; ch < NCH; ch++) {
        const int k0 = ch * 32;
        if (ch) __syncthreads();
#pragma unroll
        for (int i = 0; i < 4; i++) {
            int f = tid + i * 256;
            int r = f >> 3;
            int kq = (f & 7) * 4;
            float4 v = *(const float4*)(A + (size_t)(row0 + r) * K + k0 + kq);
            if (AFFINE) {
                v.x = fmaf(v.x, scs[k0 + kq + 0], sfs[k0 + kq + 0]);
                v.y = fmaf(v.y, scs[k0 + kq + 1], sfs[k0 + kq + 1]);
                v.z = fmaf(v.z, scs[k0 + kq + 2], sfs[k0 + kq + 2]);
                v.w = fmaf(v.w, scs[k0 + kq + 3], sfs[k0 + kq + 3]);
            }
            uint32_t h0, l0, h1, l1;
            split2_bf16(v.x, v.y, h0, l0);
            split2_bf16(v.z, v.w, h1, l1);
            int p = kq >> 1;
            Ah[r * ASTR + p] = h0; Ah[r * ASTR + p + 1] = h1;
            Al[r * ASTR + p] = l0; Al[r * ASTR + p + 1] = l1;
        }
        const int NBT = BN / 64;
#pragma unroll
        for (int i = 0; i < NBT; i++) {
            int f = tid + i * 256;
            int pr = f & 15;
            int c = (f >> 4) * 4;
            const float* Wp = W + (size_t)(k0 + 2 * pr) * CO + col0 + c;
            float4 w0 = *(const float4*)Wp;
            float4 w1 = *(const float4*)(Wp + CO);
            uint32_t h, l;
            split2_bf16(w0.x, w1.x, h, l);
            Bh[(c + 0) * BSTR + pr] = h; Bl[(c + 0) * BSTR + pr] = l;
            split2_bf16(w0.y, w1.y, h, l);
            Bh[(c + 1) * BSTR + pr] = h; Bl[(c + 1) * BSTR + pr] = l;
            split2_bf16(w0.z, w1.z, h, l);
            Bh[(c + 2) * BSTR + pr] = h; Bl[(c + 2) * BSTR + pr] = l;
            split2_bf16(w0.w, w1.w, h, l);
            Bh[(c + 3) * BSTR + pr] = h; Bl[(c + 3) * BSTR + pr] = l;
        }
        __syncthreads();
#pragma unroll
        for (int ks = 0; ks < 2; ks++) {
            const int kp = ks * 8;
#pragma unroll
            for (int t = 0; t < 2; t++) {
                const int r = warpM * 32 + t * 16 + g;
                uint32_t ah[4], al[4];
                ah[0] = Ah[r * ASTR + kp + kk];
                ah[1] = Ah[(r + 8) * ASTR + kp + kk];
                ah[2] = Ah[r * ASTR + kp + kk + 4];
                ah[3] = Ah[(r + 8) * ASTR + kp + kk + 4];
                al[0] = Al[r * ASTR + kp + kk];
                al[1] = Al[(r + 8) * ASTR + kp + kk];
                al[2] = Al[r * ASTR + kp + kk + 4];
                al[3] = Al[(r + 8) * ASTR + kp + kk + 4];
#pragma unroll
                for (int j = 0; j < NT; j++) {
                    int n = warpN * WN + j * 8 + g;
                    uint32_t b0h = Bh[n * BSTR + kp + kk];
                    uint32_t b1h = Bh[n * BSTR + kp + kk + 4];
                    uint32_t b0l = Bl[n * BSTR + kp + kk];
                    uint32_t b1l = Bl[n * BSTR + kp + kk + 4];
                    mma_bf16(acc[t][j], ah, b0h, b1h);
                    mma_bf16(acc[t][j], al, b0h, b1h);
                    mma_bf16(acc[t][j], ah, b0l, b1l);
                }
            }
        }
    }

#pragma unroll
    for (int t = 0; t < 2; t++) {
        const int r = row0 + warpM * 32 + t * 16 + g;
#pragma unroll
        for (int j = 0; j < NT; j++) {
            const int c = col0 + warpN * WN + j * 8 + 2 * kk;
            float2 v1 = make_float2(acc[t][j][0], acc[t][j][1]);
            float2 v2 = make_float2(acc[t][j][2], acc[t][j][3]);
            if (EPI == 1) {
                float2 bb = *(const float2*)(bias + c);
                v1.x = fmaxf(v1.x + bb.x, 0.f);
                v1.y = fmaxf(v1.y + bb.y, 0.f);
                v2.x = fmaxf(v2.x + bb.x, 0.f);
                v2.y = fmaxf(v2.y + bb.y, 0.f);
            }
            *(float2*)(out + (size_t)r * CO + c) = v1;
            *(float2*)(out + (size_t)(r + 8) * CO + c) = v2;
        }
    }
}

// ---------------- fp32 GEMM (layer 4: 64 -> 32), writes z only ----------------
template<int BN_T, int TN_T, bool AFFINE>
__global__ __launch_bounds__(256, 2)
void gemm_kernel(const float* __restrict__ A, const float* __restrict__ W,
                 float* __restrict__ out, int K, int Co) {
    __shared__ float As[16][128];
    __shared__ float Ws[16][BN_T];
    __shared__ float sc_sh[256], sf_sh[256];
    int tid = threadIdx.x;
    int tx = tid & 15, ty = tid >> 4;
    int row0 = blockIdx.y * 128;
    int col0 = blockIdx.x * BN_T;
    if (AFFINE) {
        for (int i = tid; i < K; i += 256) { sc_sh[i] = g_scaleA[i]; sf_sh[i] = g_shiftA[i]; }
    }
    float acc[8][TN_T];
#pragma unroll
    for (int i = 0; i < 8; i++)
#pragma unroll
        for (int j = 0; j < TN_T; j++) acc[i][j] = 0.f;
    if (AFFINE) __syncthreads();
    for (int k0 = 0; k0 < K; k0 += 16) {
#pragma unroll
        for (int i = 0; i < 2; i++) {
            int f = tid * 2 + i;
            int r = f >> 2;
            int kq = (f & 3) * 4;
            float4 v = *(const float4*)(A + (size_t)(row0 + r) * K + k0 + kq);
            if (AFFINE) {
                v.x = fmaf(v.x, sc_sh[k0 + kq + 0], sf_sh[k0 + kq + 0]);
                v.y = fmaf(v.y, sc_sh[k0 + kq + 1], sf_sh[k0 + kq + 1]);
                v.z = fmaf(v.z, sc_sh[k0 + kq + 2], sf_sh[k0 + kq + 2]);
                v.w = fmaf(v.w, sc_sh[k0 + kq + 3], sf_sh[k0 + kq + 3]);
            }
            As[kq + 0][r] = v.x; As[kq + 1][r] = v.y;
            As[kq + 2][r] = v.z; As[kq + 3][r] = v.w;
        }
        {
            const int NF4 = 16 * BN_T / 4;
#pragma unroll
            for (int i = 0; i < (NF4 + 255) / 256; i++) {
                int f = tid + i * 256;
                if ((NF4 % 256 == 0) || f < NF4) {
                    int k = f / (BN_T / 4);
                    int c = (f % (BN_T / 4)) * 4;
                    float4 v = *(const float4*)(W + (size_t)(k0 + k) * Co + col0 + c);
                    Ws[k][c + 0] = v.x; Ws[k][c + 1] = v.y;
                    Ws[k][c + 2] = v.z; Ws[k][c + 3] = v.w;
                }
            }
        }
        __syncthreads();
#pragma unroll
        for (int kk = 0; kk < 16; kk++) {
            float a[8], w[TN_T];
            float4 a0 = *(const float4*)&As[kk][ty * 4];
            float4 a1 = *(const float4*)&As[kk][64 + ty * 4];
            a[0] = a0.x; a[1] = a0.y; a[2] = a0.z; a[3] = a0.w;
            a[4] = a1.x; a[5] = a1.y; a[6] = a1.z; a[7] = a1.w;
            if (TN_T == 4) {
                float4 w0 = *(const float4*)&Ws[kk][tx * 4];
                w[0] = w0.x; w[1] = w0.y; w[2] = w0.z; w[3] = w0.w;
            } else {
                float2 w0 = *(const float2*)&Ws[kk][tx * 2];
                w[0] = w0.x; w[1] = w0.y;
            }
#pragma unroll
            for (int i = 0; i < 8; i++)
#pragma unroll
                for (int j = 0; j < TN_T; j++) acc[i][j] = fmaf(a[i], w[j], acc[i][j]);
        }
        __syncthreads();
    }
#pragma unroll
    for (int i = 0; i < 8; i++) {
        int r = row0 + ((i < 4) ? (ty * 4 + i) : (64 + ty * 4 + i - 4));
        if (TN_T >= 4) {
            int c = col0 + tx * 4;
            *(float4*)(out + (size_t)r * Co + c) =
                make_float4(acc[i][0], acc[i][1], acc[i][2], acc[i][3]);
        } else {
            int c = col0 + tx * 2;
            *(float2*)(out + (size_t)r * Co + c) = make_float2(acc[i][0], acc[i][1]);
        }
    }
}

// ---------------- BN stats helpers ----------------
template<int C>
__global__ void stats_only_kernel(const float* __restrict__ y, int zone) {
    const int c4n = C / 4;
    const int ROWS = 256 / c4n;
    int cc = threadIdx.x % c4n;
    int rg = threadIdx.x / c4n;
    float s[4] = {0, 0, 0, 0}, q[4] = {0, 0, 0, 0};
    for (int r = blockIdx.x * ROWS + rg; r < N_NODES; r += gridDim.x * ROWS) {
        float4 v = *((const float4*)(y + (size_t)r * C) + cc);
        s[0] += v.x; q[0] += v.x * v.x;
        s[1] += v.y; q[1] += v.y * v.y;
        s[2] += v.z; q[2] += v.z * v.z;
        s[3] += v.w; q[3] += v.w * v.w;
    }
    __shared__ float shs[256 * 4], shq[256 * 4];
#pragma unroll
    for (int j = 0; j < 4; j++) { shs[threadIdx.x * 4 + j] = s[j]; shq[threadIdx.x * 4 + j] = q[j]; }
    __syncthreads();
    if (rg == 0) {
#pragma unroll 1
        for (int g = 1; g < ROWS; g++) {
            int base = (g * c4n + cc) * 4;
#pragma unroll
            for (int j = 0; j < 4; j++) { s[j] += shs[base + j]; q[j] += shq[base + j]; }
        }
#pragma unroll
        for (int j = 0; j < 4; j++) {
            atomicAdd(&g_sum[zone * MAXC + cc * 4 + j],   (double)s[j]);
            atomicAdd(&g_sumsq[zone * MAXC + cc * 4 + j], (double)q[j]);
        }
    }
}

__global__ void bn_finalize_kernel(const float* __restrict__ gam, const float* __restrict__ bet,
                                   int C, float* __restrict__ oS, float* __restrict__ oH,
                                   int zone) {
    int c = threadIdx.x;
    if (c >= C) return;
    double mean = g_sum[zone * MAXC + c] / (double)N_NODES;
    double var = g_sumsq[zone * MAXC + c] / (double)N_NODES - mean * mean;
    double sc = (double)gam[c] / sqrt(var + (double)BN_EPS);
    oS[c] = (float)sc;
    oH[c] = bet[c] - (float)(mean * sc);
}

// ---------------- gate network (stats fused) ----------------
__global__ void gate1_kernel(const float* __restrict__ y4, const float* __restrict__ gW1,
                             const float* __restrict__ gb1, float* __restrict__ outz) {
    __shared__ float w[32 * 16];
    __shared__ float bb[16], sc[32], sf[32];
    __shared__ float csum[16], csq[16];
    int tid = threadIdx.x;
    int lane = tid & 31;
    for (int i = tid; i < 512; i += 256) w[i] = gW1[i];
    if (tid < 16) { bb[tid] = gb1[tid]; csum[tid] = 0.f; csq[tid] = 0.f; }
    if (tid < 32) { sc[tid] = g_scale4[tid]; sf[tid] = g_shift4[tid]; }
    __syncthreads();
    int row = blockIdx.x * 256 + tid;
    float h[32];
#pragma unroll
    for (int k4 = 0; k4 < 8; k4++) {
        float4 v = *((const float4*)(y4 + (size_t)row * 32) + k4);
        h[k4 * 4 + 0] = fmaf(v.x, sc[k4 * 4 + 0], sf[k4 * 4 + 0]);
        h[k4 * 4 + 1] = fmaf(v.y, sc[k4 * 4 + 1], sf[k4 * 4 + 1]);
        h[k4 * 4 + 2] = fmaf(v.z, sc[k4 * 4 + 2], sf[k4 * 4 + 2]);
        h[k4 * 4 + 3] = fmaf(v.w, sc[k4 * 4 + 3], sf[k4 * 4 + 3]);
    }
    float acc[16];
#pragma unroll
    for (int j = 0; j < 16; j++) acc[j] = bb[j];
#pragma unroll
    for (int k = 0; k < 32; k++)
#pragma unroll
        for (int j = 0; j < 16; j++) acc[j] = fmaf(h[k], w[k * 16 + j], acc[j]);
#pragma unroll
    for (int j4 = 0; j4 < 4; j4++)
        *((float4*)(outz + (size_t)row * 16) + j4) =
            make_float4(acc[j4 * 4], acc[j4 * 4 + 1], acc[j4 * 4 + 2], acc[j4 * 4 + 3]);
#pragma unroll
    for (int j = 0; j < 16; j++) {
        float sv = acc[j], qv = acc[j] * acc[j];
#pragma unroll
        for (int o = 16; o; o >>= 1) {
            sv += __shfl_xor_sync(0xffffffffu, sv, o);
            qv += __shfl_xor_sync(0xffffffffu, qv, o);
        }
        if (lane == 0) { atomicAdd(&csum[j], sv); atomicAdd(&csq[j], qv); }
    }
    __syncthreads();
    if (tid < 16) {
        atomicAdd(&g_sum[4 * MAXC + tid],   (double)csum[tid]);
        atomicAdd(&g_sumsq[4 * MAXC + tid], (double)csq[tid]);
    }
}

__global__ void gate2_kernel(const float* __restrict__ z, const float* __restrict__ gW2,
                             const float* __restrict__ gb2, float* __restrict__ out) {
    __shared__ float w[16], sc[16], sf[16], b0;
    __shared__ float ws[8], wq[8];
    int tid = threadIdx.x;
    int lane = tid & 31, wid = tid >> 5;
    if (tid < 16) { w[tid] = gW2[tid]; sc[tid] = g_scaleG1[tid]; sf[tid] = g_shiftG1[tid]; }
    if (tid == 0) b0 = gb2[0];
    __syncthreads();
    int row = blockIdx.x * 256 + tid;
    float acc = b0;
#pragma unroll
    for (int k4 = 0; k4 < 4; k4++) {
        float4 v = *((const float4*)(z + (size_t)row * 16) + k4);
        acc = fmaf(fmaxf(fmaf(v.x, sc[k4 * 4 + 0], sf[k4 * 4 + 0]), 0.f), w[k4 * 4 + 0], acc);
        acc = fmaf(fmaxf(fmaf(v.y, sc[k4 * 4 + 1], sf[k4 * 4 + 1]), 0.f), w[k4 * 4 + 1], acc);
        acc = fmaf(fmaxf(fmaf(v.z, sc[k4 * 4 + 2], sf[k4 * 4 + 2]), 0.f), w[k4 * 4 + 2], acc);
        acc = fmaf(fmaxf(fmaf(v.w, sc[k4 * 4 + 3], sf[k4 * 4 + 3]), 0.f), w[k4 * 4 + 3], acc);
    }
    out[row] = acc;
    float sv = acc, qv = acc * acc;
#pragma unroll
    for (int o = 16; o; o >>= 1) {
        sv += __shfl_xor_sync(0xffffffffu, sv, o);
        qv += __shfl_xor_sync(0xffffffffu, qv, o);
    }
    if (lane == 0) { ws[wid] = sv; wq[wid] = qv; }
    __syncthreads();
    if (tid == 0) {
        float ts = 0.f, tq = 0.f;
#pragma unroll
        for (int i = 0; i < 8; i++) { ts += ws[i]; tq += wq[i]; }
        atomicAdd(&g_sum[5 * MAXC],   (double)ts);
        atomicAdd(&g_sumsq[5 * MAXC], (double)tq);
    }
}

// ---------------- pooling + FC + softmax ----------------
__global__ void pool_fc_kernel(const float* __restrict__ y4, const float* __restrict__ g2,
                               const float* __restrict__ fcW, const float* __restrict__ fcb,
                               float* __restrict__ out) {
    int warp = (blockIdx.x * blockDim.x + threadIdx.x) >> 5;
    int lane = threadIdx.x & 31;
    if (warp >= NGRAPH) return;
    int n0 = warp * ONE_STEP;
    const unsigned FULL = 0xffffffffu;
    float scG = g_scaleG2[0], sfG = g_shiftG2[0];
    float gv = (lane < ONE_STEP) ? fmaxf(fmaf(g2[n0 + lane], scG, sfG), 0.f) : -INFINITY;
    float m = gv;
#pragma unroll
    for (int o = 16; o; o >>= 1) m = fmaxf(m, __shfl_xor_sync(FULL, m, o));
    float ev = (lane < ONE_STEP) ? expf(gv - m) : 0.f;
    float s = ev;
#pragma unroll
    for (int o = 16; o; o >>= 1) s += __shfl_xor_sync(FULL, s, o);
    float inv = 1.0f / s;
    float sc4 = g_scale4[lane], sf4 = g_shift4[lane];
    float pooled = 0.f;
#pragma unroll
    for (int i = 0; i < ONE_STEP; i++) {
        float a = __shfl_sync(FULL, ev, i) * inv;
        float hv = fmaf(y4[(size_t)(n0 + i) * 32 + lane], sc4, sf4);
        pooled = fmaf(a, hv, pooled);
    }
    float logits[10];
#pragma unroll
    for (int j = 0; j < 10; j++) {
        float p = pooled * fcW[lane * 10 + j];
#pragma unroll
        for (int o = 16; o; o >>= 1) p += __shfl_xor_sync(FULL, p, o);
        logits[j] = p + fcb[j];
    }
    if (lane == 0) {
        float mx = logits[0];
#pragma unroll
        for (int j = 1; j < 10; j++) mx = fmaxf(mx, logits[j]);
        float ss = 0.f;
        float e[10];
#pragma unroll
        for (int j = 0; j < 10; j++) { e[j] = expf(logits[j] - mx); ss += e[j]; }
        float invs = 1.0f / ss;
#pragma unroll
        for (int j = 0; j < 10; j++) out[warp * 10 + j] = e[j] * invs;
    }
}

// ---------------- host orchestration ----------------
extern "C" void kernel_launch(void* const* d_in, const int* in_sizes, int n_in,
                              void* d_out, int out_size) {
    const float* x    = (const float*)d_in[0];
    const int*   ei   = (const int*)d_in[1];
    const float* W1   = (const float*)d_in[2];
    const float* b1   = (const float*)d_in[3];
    const float* bn1g = (const float*)d_in[4];
    const float* bn1b = (const float*)d_in[5];
    const float* W2   = (const float*)d_in[6];
    const float* b2   = (const float*)d_in[7];
    const float* bn2g = (const float*)d_in[8];
    const float* bn2b = (const float*)d_in[9];
    const float* W3   = (const float*)d_in[10];
    const float* b3   = (const float*)d_in[11];
    const float* bn3g = (const float*)d_in[12];
    const float* bn3b = (const float*)d_in[13];
    const float* W4   = (const float*)d_in[14];
    const float* b4   = (const float*)d_in[15];
    const float* bn4g = (const float*)d_in[16];
    const float* bn4b = (const float*)d_in[17];
    const float* gW1  = (const float*)d_in[18];
    const float* gb1  = (const float*)d_in[19];
    const float* gbn1g = (const float*)d_in[20];
    const float* gbn1b = (const float*)d_in[21];
    const float* gW2  = (const float*)d_in[22];
    const float* gb2  = (const float*)d_in[23];
    const float* gbn2g = (const float*)d_in[24];
    const float* gbn2b = (const float*)d_in[25];
    const float* fcW  = (const float*)d_in[26];
    const float* fcb  = (const float*)d_in[27];
    float* out = (float*)d_out;

    float *buf0, *buf1, *buf2;
    float *scA, *shA, *sc4, *sh4, *scG1, *shG1, *scG2, *shG2;
    cudaGetSymbolAddress((void**)&buf0, g_buf0);
    cudaGetSymbolAddress((void**)&buf1, g_buf1);
    cudaGetSymbolAddress((void**)&buf2, g_buf2);
    cudaGetSymbolAddress((void**)&scA, g_scaleA);
    cudaGetSymbolAddress((void**)&shA, g_shiftA);
    cudaGetSymbolAddress((void**)&sc4, g_scale4);
    cudaGetSymbolAddress((void**)&sh4, g_shift4);
    cudaGetSymbolAddress((void**)&scG1, g_scaleG1);
    cudaGetSymbolAddress((void**)&shG1, g_shiftG1);
    cudaGetSymbolAddress((void**)&scG2, g_scaleG2);
    cudaGetSymbolAddress((void**)&shG2, g_shiftG2);

    const int GRID = N_NODES / 128;  // 896
    const int EB = (N_EDGES + 255) / 256;
    const int SM_L1 = (2 * 128 * 20 + 2 * 128 * 20) * 4;             // 40960
    const int SM_L2 = (2 * 128 * 20 + 2 * 128 * 20) * 4;             // 40960
    const int SM_L3 = (2 * 128 * 20 + 2 * 64 * 20 + 2 * 256) * 4;    // 32768
    cudaFuncSetAttribute((const void*)mma_gemm_kernel<128, 128, 512, false, 0>,
                         cudaFuncAttributeMaxDynamicSharedMemorySize, SM_L1);
    cudaFuncSetAttribute((const void*)mma_gemm_kernel<256, 128, 128, false, 1>,
                         cudaFuncAttributeMaxDynamicSharedMemorySize, SM_L2);
    cudaFuncSetAttribute((const void*)mma_gemm_kernel<64, 64, 256, true, 0>,
                         cudaFuncAttributeMaxDynamicSharedMemorySize, SM_L3);

    // ---- CSR build + zero stats zones (dis fused into scan1; sw written at scatter) ----
    cnt_zero_kernel<<<NBLK, 256>>>();
    cnt_count_kernel<<<EB, 256>>>(ei);
    scan1_kernel<<<NBLK, 256>>>();
    scan2_kernel<<<1, 512>>>();
    scan3_kernel<<<NBLK, 256>>>();
    scatter_kernel<<<EB, 256>>>(ei);

    // ---- Layer 1 (512 -> 128): GEMM -> CSR agg (+bias+relu+stats z0) ----
    mma_gemm_kernel<128, 128, 512, false, 0><<<dim3(1, GRID), 256, SM_L1>>>(x, W1, nullptr, buf1);
    csr_agg_kernel<128, false, true><<<1792, 256>>>(buf1, b1, buf0, 0);
    bn_finalize_kernel<<<1, 128>>>(bn1g, bn1b, 128, scA, shA, 0);

    // ---- Layer 2 (128 -> 256): CSR agg first (BN fused), GEMM + relu, stats pass z1 ----
    csr_agg_kernel<128, true, false><<<1792, 256>>>(buf0, nullptr, buf2, 0);
    mma_gemm_kernel<256, 128, 128, false, 1><<<dim3(2, GRID), 256, SM_L2>>>(buf2, W2, b2, buf0);
    stats_only_kernel<256><<<512, 256>>>(buf0, 1);
    bn_finalize_kernel<<<1, 256>>>(bn2g, bn2b, 256, scA, shA, 1);

    // ---- Layer 3 (256 -> 64): GEMM (BN fused) -> CSR agg (+bias+relu+stats z2) ----
    mma_gemm_kernel<64, 64, 256, true, 0><<<dim3(1, GRID), 256, SM_L3>>>(buf0, W3, nullptr, buf1);
    csr_agg_kernel<64, false, true><<<1792, 256>>>(buf1, b3, buf0, 2);
    bn_finalize_kernel<<<1, 64>>>(bn3g, bn3b, 64, scA, shA, 2);

    // ---- Layer 4 (64 -> 32): fp32 GEMM (BN fused) -> CSR agg (+stats z3) ----
    gemm_kernel<32, 2, true><<<dim3(1, GRID), 256>>>(buf0, W4, buf1, 64, 32);
    csr_agg_kernel<32, false, true><<<1792, 256>>>(buf1, b4, buf0, 3);
    bn_finalize_kernel<<<1, 32>>>(bn4g, bn4b, 32, sc4, sh4, 3);

    // ---- gate layer 1 (stats fused, z4) ----
    gate1_kernel<<<N_NODES / 256, 256>>>(buf0, gW1, gb1, buf1);
    bn_finalize_kernel<<<1, 16>>>(gbn1g, gbn1b, 16, scG1, shG1, 4);

    // ---- gate layer 2 (stats fused, z5) ----
    gate2_kernel<<<N_NODES / 256, 256>>>(buf1, gW2, gb2, buf2);
    bn_finalize_kernel<<<1, 32>>>(gbn2g, gbn2b, 1, scG2, shG2, 5);

    // ---- segment softmax pooling + FC + softmax ----
    pool_fc_kernel<<<(NGRAPH * 32 + 255) / 256, 256>>>(buf0, buf2, fcW, fcb, out);
}